// round 5
// baseline (speedup 1.0000x reference)
#include <cuda_runtime.h>
#include <math.h>

#define Bv 8
#define Cv 64
#define Hv 128
#define Wv 128
#define Ov 64
#define HWv (Hv*Wv)

// scratch (__device__ globals; no allocation allowed)
__device__ float g_offset[Bv*18*HWv];   // (B,18,H,W)
__device__ float g_mask[Bv*9*HWv];      // (B,9,H,W)
__device__ float g_xt[(size_t)Bv*HWv*Cv]; // (B,H,W,C)
__device__ float g_whP[Cv*18*16];
__device__ float g_wvP[Cv*18*16];
__device__ float g_wmP[Cv*9*12];
__device__ float g_wdT[Ov*576];         // [o][j] float4 j = k*16 + c/4
__device__ float g_psum[Ov*Bv];
__device__ float g_psq[Ov*Bv];
__device__ float g_mean[Ov];
__device__ float g_rstd[Ov];

// ---------------------------------------------------------------------------
// weight packer
// ---------------------------------------------------------------------------
__global__ void pack_kernel(const float* __restrict__ wh, const float* __restrict__ wv,
                            const float* __restrict__ wm, const float* __restrict__ wd) {
    int idx = blockIdx.x*256 + threadIdx.x;
    if (idx < 18432) {
        int c = idx/288, r = idx - c*288, o = r >> 4, k = r & 15;
        g_whP[idx] = (k < 15) ? wh[(o*Cv + c)*15 + k] : 0.f;
        g_wvP[idx] = (k < 15) ? wv[(o*Cv + c)*15 + k] : 0.f;
    } else if (idx < 18432 + 6912) {
        int j = idx - 18432;
        int c = j/108, r = j - c*108, o = r/12, k = r - o*12;
        g_wmP[j] = (k < 9) ? wm[(o*Cv + c)*9 + k] : 0.f;
    } else if (idx < 18432 + 6912 + 36864) {
        int j = idx - 18432 - 6912;
        int o = j/576, r = j - o*576, k = r >> 6, c = r & 63;
        g_wdT[j] = wd[(o*Cv + c)*9 + k];
    }
}

// ---------------------------------------------------------------------------
// x (B,C,HW) -> xt (B,HW,C)
// ---------------------------------------------------------------------------
__global__ void transpose_kernel(const float* __restrict__ x) {
    __shared__ float t[32][33];
    int b = blockIdx.z;
    int hw0 = blockIdx.x * 32;
    int c0  = blockIdx.y * 32;
    int tx = threadIdx.x, ty = threadIdx.y;
    #pragma unroll
    for (int j = 0; j < 4; j++) {
        int c = c0 + ty + j*8;
        t[ty + j*8][tx] = x[((size_t)b*Cv + c)*HWv + hw0 + tx];
    }
    __syncthreads();
    #pragma unroll
    for (int j = 0; j < 4; j++) {
        int hw = hw0 + ty + j*8;
        g_xt[((size_t)b*HWv + hw)*Cv + c0 + tx] = t[tx][ty + j*8];
    }
}

// ---------------------------------------------------------------------------
// fused offset(18ch) + mask(9ch): 32x8 tile, 256 threads, 1 px/thread
// warp = one pixel row -> conflict-free LDS; double-buffered tile
// ---------------------------------------------------------------------------
__global__ void __launch_bounds__(256, 2) offmask_kernel(
    const float* __restrict__ x,
    const float* __restrict__ bh, const float* __restrict__ bv,
    const float* __restrict__ bm)
{
    __shared__ float tiles[2][22*47];
    int b  = blockIdx.z;
    int h0 = blockIdx.y * 8;
    int wb = blockIdx.x * 32;
    int tid = threadIdx.x;
    int tx = tid & 31, ty = tid >> 5;
    int h = h0 + ty;
    int w = wb + tx;

    // precompute 4 load slots per thread (tile is 22 x 46, stride 47)
    int soff[4], sidx[4];
    #pragma unroll
    for (int s = 0; s < 4; s++) {
        int i = tid + s*256;
        if (i < 22*46) {
            int r = i / 46, cc = i - r*46;
            int gh = h0 + r - 7, gw = wb + cc - 7;
            sidx[s] = r*47 + cc;
            soff[s] = (gh >= 0 && gh < Hv && gw >= 0 && gw < Wv) ? gh*Wv + gw : -1;
        } else { sidx[s] = -1; soff[s] = -1; }
    }

    float acc[18], am[9];
    #pragma unroll
    for (int o = 0; o < 18; o++) acc[o] = bh[o] + bv[o];
    #pragma unroll
    for (int o = 0; o < 9; o++)  am[o] = bm[o];

    const float* xb = x + (size_t)b*Cv*HWv;

    // preload c=0
    #pragma unroll
    for (int s = 0; s < 4; s++)
        if (sidx[s] >= 0) tiles[0][sidx[s]] = (soff[s] >= 0) ? __ldg(xb + soff[s]) : 0.f;

    for (int c = 0; c < Cv; c++) {
        __syncthreads();
        if (c + 1 < Cv) {
            const float* xc = xb + (c+1)*HWv;
            float* dst = tiles[(c+1) & 1];
            #pragma unroll
            for (int s = 0; s < 4; s++)
                if (sidx[s] >= 0) dst[sidx[s]] = (soff[s] >= 0) ? __ldg(xc + soff[s]) : 0.f;
        }
        const float* tile = tiles[c & 1];

        float xr[15], xcA[15];
        #pragma unroll
        for (int i = 0; i < 15; i++) xr[i]  = tile[(ty+7)*47 + tx + i];
        #pragma unroll
        for (int i = 0; i < 15; i++) xcA[i] = tile[(ty+i)*47 + tx + 7];
        float t00 = tile[(ty+6)*47 + tx + 6];
        float t01 = tile[(ty+6)*47 + tx + 8];
        float t10 = tile[(ty+8)*47 + tx + 6];
        float t11 = tile[(ty+8)*47 + tx + 8];

        const float4* whc = (const float4*)(g_whP + c*288);
        const float4* wvc = (const float4*)(g_wvP + c*288);
        const float4* wmc = (const float4*)(g_wmP + c*108);
        #pragma unroll
        for (int o = 0; o < 18; o++) {
            float4 q0 = whc[o*4+0], q1 = whc[o*4+1], q2 = whc[o*4+2], q3 = whc[o*4+3];
            float wkh[15] = {q0.x,q0.y,q0.z,q0.w, q1.x,q1.y,q1.z,q1.w,
                             q2.x,q2.y,q2.z,q2.w, q3.x,q3.y,q3.z};
            float a = acc[o];
            #pragma unroll
            for (int k = 0; k < 15; k++) a = fmaf(xr[k], wkh[k], a);
            float4 v0 = wvc[o*4+0], v1 = wvc[o*4+1], v2 = wvc[o*4+2], v3 = wvc[o*4+3];
            float wkv[15] = {v0.x,v0.y,v0.z,v0.w, v1.x,v1.y,v1.z,v1.w,
                             v2.x,v2.y,v2.z,v2.w, v3.x,v3.y,v3.z};
            #pragma unroll
            for (int k = 0; k < 15; k++) a = fmaf(xcA[k], wkv[k], a);
            acc[o] = a;
        }
        #pragma unroll
        for (int o = 0; o < 9; o++) {
            float4 q0 = wmc[o*3], q1 = wmc[o*3+1], q2 = wmc[o*3+2];
            float m = am[o];
            m = fmaf(t00,    q0.x, m);
            m = fmaf(xcA[6], q0.y, m);
            m = fmaf(t01,    q0.z, m);
            m = fmaf(xr[6],  q0.w, m);
            m = fmaf(xr[7],  q1.x, m);
            m = fmaf(xr[8],  q1.y, m);
            m = fmaf(t10,    q1.z, m);
            m = fmaf(xcA[8], q1.w, m);
            m = fmaf(t11,    q2.x, m);
            am[o] = m;
        }
    }

    #pragma unroll
    for (int o = 0; o < 18; o++)
        g_offset[((b*18 + o)*Hv + h)*Wv + w] = acc[o];
    #pragma unroll
    for (int o = 0; o < 9; o++)
        g_mask[((b*9 + o)*Hv + h)*Wv + w] = 1.f/(1.f + __expf(-am[o]));
}

// ---------------------------------------------------------------------------
// deform: 16-px tile; stage A interp; stage B gather -> ss (sliced layout);
// stage C 4o x 4p x Ksplit-4 with bank-conflict-free slice layout
// rows (weights and ss): 4 slices x 37 float4, row stride 149 float4 (596 f)
// ---------------------------------------------------------------------------
#define ROW_F4 149
#define SLICE_F4 37
#define OFF_SS   (64*ROW_F4*4)                    // floats: 38144
#define OFF_RED  (OFF_SS + 16*ROW_F4*4)           // + 9536
#define OFF_SAY  (OFF_RED + 4096)
#define OFF_SAX  (OFF_SAY + 144)
#define OFF_SAW  (OFF_SAX + 144)
#define SMEM_FLOATS (OFF_SAW + 576)

__global__ void __launch_bounds__(256, 1) deform_kernel(float* __restrict__ out) {
    extern __shared__ float smem[];
    float4* swf = (float4*)smem;                  // 64 rows x 149 f4
    float4* ssf = (float4*)(smem + OFF_SS);       // 16 rows x 149 f4
    float*  red = smem + OFF_RED;
    int*   sAy  = (int*)(smem + OFF_SAY);
    int*   sAx  = (int*)(smem + OFF_SAX);
    float4* sAw = (float4*)(smem + OFF_SAW);
    int tid = threadIdx.x;

    // load weights into sliced layout
    const float4* wt4 = (const float4*)g_wdT;
    for (int i = tid; i < 64*144; i += 256) {
        int o = i / 144, j = i - o*144;
        swf[o*ROW_F4 + (j/36)*SLICE_F4 + (j%36)] = wt4[i];
    }

    int h  = blockIdx.x >> 3;
    int w0 = (blockIdx.x & 7) << 4;

    // stage C mapping: warp spans ks(4) x pg(4) x og(2)
    int ks = tid & 3;
    int pg = (tid >> 2) & 3;
    int og = tid >> 4;           // 0..15, o = og*4 + oi
    const float4* w0p = swf + (og*4+0)*ROW_F4 + ks*SLICE_F4;
    const float4* w1p = swf + (og*4+1)*ROW_F4 + ks*SLICE_F4;
    const float4* w2p = swf + (og*4+2)*ROW_F4 + ks*SLICE_F4;
    const float4* w3p = swf + (og*4+3)*ROW_F4 + ks*SLICE_F4;
    const float4* p0p = ssf + (pg*4+0)*ROW_F4 + ks*SLICE_F4;
    const float4* p1p = ssf + (pg*4+1)*ROW_F4 + ks*SLICE_F4;
    const float4* p2p = ssf + (pg*4+2)*ROW_F4 + ks*SLICE_F4;
    const float4* p3p = ssf + (pg*4+3)*ROW_F4 + ks*SLICE_F4;

    // reducer mapping: o = (tid>>4)*4 + (tid&3), pixels ((tid>>2)&3)*4 ..+3
    int r_og = tid >> 4, r_oi = tid & 3, r_pg = (tid >> 2) & 3;

    for (int b = 0; b < Bv; b++) {
        __syncthreads();
        if (tid < 144) {
            int p = tid / 9, k = tid - p*9;
            int w = w0 + p;
            int ky = k / 3, kx = k - ky*3;
            float dy = g_offset[((b*18 + 2*k    )*Hv + h)*Wv + w];
            float dx = g_offset[((b*18 + 2*k + 1)*Hv + h)*Wv + w];
            float m  = g_mask  [((b*9  + k      )*Hv + h)*Wv + w];
            float py = (float)(h + ky - 1) + dy;
            float px = (float)(w + kx - 1) + dx;
            float y0f = floorf(py), x0f = floorf(px);
            float wy1 = py - y0f, wx1 = px - x0f;
            float wy0 = 1.f - wy1, wx0 = 1.f - wx1;
            int iy0 = (int)y0f, ix0 = (int)x0f;
            bool vy0 = (iy0 >= 0)  && (iy0 < Hv);
            bool vy1 = (iy0 >= -1) && (iy0 < Hv-1);
            bool vx0 = (ix0 >= 0)  && (ix0 < Wv);
            bool vx1 = (ix0 >= -1) && (ix0 < Wv-1);
            sAy[tid] = iy0; sAx[tid] = ix0;
            sAw[tid] = make_float4((vy0 && vx0) ? m*wy0*wx0 : 0.f,
                                   (vy0 && vx1) ? m*wy0*wx1 : 0.f,
                                   (vy1 && vx0) ? m*wy1*wx0 : 0.f,
                                   (vy1 && vx1) ? m*wy1*wx1 : 0.f);
        }
        __syncthreads();

        const float4* xb4 = (const float4*)g_xt + (size_t)b*HWv*16;
        #pragma unroll
        for (int itb = 0; itb < 9; itb++) {
            int it = itb*256 + tid;       // 0..2303
            int pk = it >> 4, cq = it & 15;
            int iy0 = sAy[pk], ix0 = sAx[pk];
            float4 wg = sAw[pk];
            int y0c = min(Hv-1, max(0, iy0));
            int y1c = min(Hv-1, max(0, iy0 + 1));
            int x0c = min(Wv-1, max(0, ix0));
            int x1c = min(Wv-1, max(0, ix0 + 1));
            float4 v00 = xb4[(y0c*Wv + x0c)*16 + cq];
            float4 v01 = xb4[(y0c*Wv + x1c)*16 + cq];
            float4 v10 = xb4[(y1c*Wv + x0c)*16 + cq];
            float4 v11 = xb4[(y1c*Wv + x1c)*16 + cq];
            float4 r;
            r.x = fmaf(wg.w, v11.x, fmaf(wg.z, v10.x, fmaf(wg.y, v01.x, wg.x*v00.x)));
            r.y = fmaf(wg.w, v11.y, fmaf(wg.z, v10.y, fmaf(wg.y, v01.y, wg.x*v00.y)));
            r.z = fmaf(wg.w, v11.z, fmaf(wg.z, v10.z, fmaf(wg.y, v01.z, wg.x*v00.z)));
            r.w = fmaf(wg.w, v11.w, fmaf(wg.z, v10.w, fmaf(wg.y, v01.w, wg.x*v00.w)));
            int p = pk / 9, k = pk - p*9;
            int j = k*16 + cq;
            ssf[p*ROW_F4 + (j/36)*SLICE_F4 + (j%36)] = r;
        }
        __syncthreads();

        // stage C: 16 accumulators (4 o x 4 p), 36 K-chunks of float4
        float a00=0,a01=0,a02=0,a03=0, a10=0,a11=0,a12=0,a13=0;
        float a20=0,a21=0,a22=0,a23=0, a30=0,a31=0,a32=0,a33=0;
        #pragma unroll 4
        for (int q = 0; q < 36; q++) {
            float4 qa = w0p[q], qb = w1p[q], qc = w2p[q], qd = w3p[q];
            float4 s0 = p0p[q], s1 = p1p[q], s2 = p2p[q], s3 = p3p[q];
            a00=fmaf(qa.x,s0.x,a00); a00=fmaf(qa.y,s0.y,a00); a00=fmaf(qa.z,s0.z,a00); a00=fmaf(qa.w,s0.w,a00);
            a01=fmaf(qa.x,s1.x,a01); a01=fmaf(qa.y,s1.y,a01); a01=fmaf(qa.z,s1.z,a01); a01=fmaf(qa.w,s1.w,a01);
            a02=fmaf(qa.x,s2.x,a02); a02=fmaf(qa.y,s2.y,a02); a02=fmaf(qa.z,s2.z,a02); a02=fmaf(qa.w,s2.w,a02);
            a03=fmaf(qa.x,s3.x,a03); a03=fmaf(qa.y,s3.y,a03); a03=fmaf(qa.z,s3.z,a03); a03=fmaf(qa.w,s3.w,a03);
            a10=fmaf(qb.x,s0.x,a10); a10=fmaf(qb.y,s0.y,a10); a10=fmaf(qb.z,s0.z,a10); a10=fmaf(qb.w,s0.w,a10);
            a11=fmaf(qb.x,s1.x,a11); a11=fmaf(qb.y,s1.y,a11); a11=fmaf(qb.z,s1.z,a11); a11=fmaf(qb.w,s1.w,a11);
            a12=fmaf(qb.x,s2.x,a12); a12=fmaf(qb.y,s2.y,a12); a12=fmaf(qb.z,s2.z,a12); a12=fmaf(qb.w,s2.w,a12);
            a13=fmaf(qb.x,s3.x,a13); a13=fmaf(qb.y,s3.y,a13); a13=fmaf(qb.z,s3.z,a13); a13=fmaf(qb.w,s3.w,a13);
            a20=fmaf(qc.x,s0.x,a20); a20=fmaf(qc.y,s0.y,a20); a20=fmaf(qc.z,s0.z,a20); a20=fmaf(qc.w,s0.w,a20);
            a21=fmaf(qc.x,s1.x,a21); a21=fmaf(qc.y,s1.y,a21); a21=fmaf(qc.z,s1.z,a21); a21=fmaf(qc.w,s1.w,a21);
            a22=fmaf(qc.x,s2.x,a22); a22=fmaf(qc.y,s2.y,a22); a22=fmaf(qc.z,s2.z,a22); a22=fmaf(qc.w,s2.w,a22);
            a23=fmaf(qc.x,s3.x,a23); a23=fmaf(qc.y,s3.y,a23); a23=fmaf(qc.z,s3.z,a23); a23=fmaf(qc.w,s3.w,a23);
            a30=fmaf(qd.x,s0.x,a30); a30=fmaf(qd.y,s0.y,a30); a30=fmaf(qd.z,s0.z,a30); a30=fmaf(qd.w,s0.w,a30);
            a31=fmaf(qd.x,s1.x,a31); a31=fmaf(qd.y,s1.y,a31); a31=fmaf(qd.z,s1.z,a31); a31=fmaf(qd.w,s1.w,a31);
            a32=fmaf(qd.x,s2.x,a32); a32=fmaf(qd.y,s2.y,a32); a32=fmaf(qd.z,s2.z,a32); a32=fmaf(qd.w,s2.w,a32);
            a33=fmaf(qd.x,s3.x,a33); a33=fmaf(qd.y,s3.y,a33); a33=fmaf(qd.z,s3.z,a33); a33=fmaf(qd.w,s3.w,a33);
        }
        // partial store: float4 index = ks*256 + og*16 + pg*4 + oi
        {
            float4* rp = (float4*)red + ks*256 + og*16 + pg*4;
            rp[0] = make_float4(a00,a01,a02,a03);
            rp[1] = make_float4(a10,a11,a12,a13);
            rp[2] = make_float4(a20,a21,a22,a23);
            rp[3] = make_float4(a30,a31,a32,a33);
        }
        __syncthreads();

        // reduce 4 K-slices
        {
            const float4* r4 = (const float4*)red;
            int base = r_og*16 + r_pg*4 + r_oi;
            float4 v0 = r4[base];
            float4 v1 = r4[256 + base];
            float4 v2 = r4[512 + base];
            float4 v3 = r4[768 + base];
            float4 res;
            res.x = (v0.x+v1.x) + (v2.x+v3.x);
            res.y = (v0.y+v1.y) + (v2.y+v3.y);
            res.z = (v0.z+v1.z) + (v2.z+v3.z);
            res.w = (v0.w+v1.w) + (v2.w+v3.w);
            int o = r_og*4 + r_oi;
            *(float4*)&out[((size_t)(b*Ov + o)*Hv + h)*Wv + w0 + r_pg*4] = res;
        }
    }
}

// ---------------------------------------------------------------------------
// BN
// ---------------------------------------------------------------------------
__global__ void reduce_kernel(const float* __restrict__ y) {
    int c = blockIdx.x, b = blockIdx.y, tid = threadIdx.x;
    const float4* p = (const float4*)y + (size_t)(b*Ov + c)*4096;
    float s = 0.f, q = 0.f;
    for (int i = tid; i < 4096; i += 256) {
        float4 v = p[i];
        s += v.x + v.y + v.z + v.w;
        q = fmaf(v.x,v.x,q); q = fmaf(v.y,v.y,q); q = fmaf(v.z,v.z,q); q = fmaf(v.w,v.w,q);
    }
    __shared__ float ssum[8], ssq[8];
    #pragma unroll
    for (int o = 16; o > 0; o >>= 1) {
        s += __shfl_down_sync(0xffffffff, s, o);
        q += __shfl_down_sync(0xffffffff, q, o);
    }
    if ((tid & 31) == 0) { ssum[tid >> 5] = s; ssq[tid >> 5] = q; }
    __syncthreads();
    if (tid < 8) {
        s = ssum[tid]; q = ssq[tid];
        #pragma unroll
        for (int o = 4; o > 0; o >>= 1) {
            s += __shfl_down_sync(0xff, s, o);
            q += __shfl_down_sync(0xff, q, o);
        }
        if (tid == 0) { g_psum[c*Bv + b] = s; g_psq[c*Bv + b] = q; }
    }
}

__global__ void stats_kernel() {
    int c = threadIdx.x;
    float s = 0.f, q = 0.f;
    for (int b = 0; b < Bv; b++) { s += g_psum[c*Bv + b]; q += g_psq[c*Bv + b]; }
    const float inv = 1.f / (float)(Bv*HWv);
    float mean = s * inv;
    float var  = q * inv - mean*mean;
    g_mean[c] = mean;
    g_rstd[c] = rsqrtf(var + 1e-5f);
}

__global__ void bn_kernel(float* __restrict__ y,
                          const float* __restrict__ gamma,
                          const float* __restrict__ beta) {
    int idx = blockIdx.x*256 + threadIdx.x;
    if (idx >= Bv*Ov*HWv/4) return;
    int c = (idx >> 12) & 63;
    float a  = g_rstd[c] * gamma[c];
    float bb = fmaf(-g_mean[c], a, beta[c]);
    float4* p = (float4*)y;
    float4 v = p[idx];
    v.x = fmaxf(fmaf(v.x, a, bb), 0.f);
    v.y = fmaxf(fmaf(v.y, a, bb), 0.f);
    v.z = fmaxf(fmaf(v.z, a, bb), 0.f);
    v.w = fmaxf(fmaf(v.w, a, bb), 0.f);
    p[idx] = v;
}

// ---------------------------------------------------------------------------
extern "C" void kernel_launch(void* const* d_in, const int* in_sizes, int n_in,
                              void* d_out, int out_size) {
    const float* x     = (const float*)d_in[0];
    const float* wh    = (const float*)d_in[1];
    const float* bh    = (const float*)d_in[2];
    const float* wv    = (const float*)d_in[3];
    const float* bv    = (const float*)d_in[4];
    const float* wm    = (const float*)d_in[5];
    const float* bm    = (const float*)d_in[6];
    const float* wd    = (const float*)d_in[7];
    const float* gamma = (const float*)d_in[8];
    const float* beta  = (const float*)d_in[9];
    float* out = (float*)d_out;

    const int deform_smem = SMEM_FLOATS * 4;   // ~206 KB
    cudaFuncSetAttribute(deform_kernel, cudaFuncAttributeMaxDynamicSharedMemorySize, deform_smem);

    pack_kernel<<<(18432 + 6912 + 36864 + 255)/256, 256>>>(wh, wv, wm, wd);
    transpose_kernel<<<dim3(HWv/32, Cv/32, Bv), dim3(32, 8)>>>(x);
    offmask_kernel<<<dim3(Wv/32, Hv/8, Bv), 256>>>(x, bh, bv, bm);
    deform_kernel<<<1024, 256, deform_smem>>>(out);
    reduce_kernel<<<dim3(Ov, Bv), 256>>>(out);
    stats_kernel<<<1, Ov>>>();
    bn_kernel<<<(Bv*Ov*HWv/4 + 255)/256, 256>>>(out, gamma, beta);
}

// round 6
// speedup vs baseline: 1.1877x; 1.1877x over previous
#include <cuda_runtime.h>
#include <math.h>

#define Bv 8
#define Cv 64
#define Hv 128
#define Wv 128
#define Ov 64
#define HWv (Hv*Wv)

// scratch (__device__ globals; no allocation allowed)
__device__ float g_offset[Bv*18*HWv];   // (B,18,H,W)
__device__ float g_mask[Bv*9*HWv];      // (B,9,H,W)
__device__ float g_xt[(size_t)Bv*HWv*Cv]; // (B,H,W,C)
__device__ float g_whP[Cv*18*16];
__device__ float g_wvP[Cv*18*16];
__device__ float g_wmP[Cv*9*12];
__device__ float g_wdT[Ov*576];         // [o][j], j = k*16 + c/4 (float4 granules)
__device__ float g_psum[Ov*Bv];
__device__ float g_psq[Ov*Bv];
__device__ float g_mean[Ov];
__device__ float g_rstd[Ov];

// ---------------------------------------------------------------------------
// weight packer
// ---------------------------------------------------------------------------
__global__ void pack_kernel(const float* __restrict__ wh, const float* __restrict__ wv,
                            const float* __restrict__ wm, const float* __restrict__ wd) {
    int idx = blockIdx.x*256 + threadIdx.x;
    if (idx < 18432) {
        int c = idx/288, r = idx - c*288, o = r >> 4, k = r & 15;
        g_whP[idx] = (k < 15) ? wh[(o*Cv + c)*15 + k] : 0.f;
        g_wvP[idx] = (k < 15) ? wv[(o*Cv + c)*15 + k] : 0.f;
    } else if (idx < 18432 + 6912) {
        int j = idx - 18432;
        int c = j/108, r = j - c*108, o = r/12, k = r - o*12;
        g_wmP[j] = (k < 9) ? wm[(o*Cv + c)*9 + k] : 0.f;
    } else if (idx < 18432 + 6912 + 36864) {
        int j = idx - 18432 - 6912;
        int o = j/576, r = j - o*576, k = r >> 6, c = r & 63;
        g_wdT[j] = wd[(o*Cv + c)*9 + k];
    }
}

// ---------------------------------------------------------------------------
// x (B,C,HW) -> xt (B,HW,C)
// ---------------------------------------------------------------------------
__global__ void transpose_kernel(const float* __restrict__ x) {
    __shared__ float t[32][33];
    int b = blockIdx.z;
    int hw0 = blockIdx.x * 32;
    int c0  = blockIdx.y * 32;
    int tx = threadIdx.x, ty = threadIdx.y;
    #pragma unroll
    for (int j = 0; j < 4; j++) {
        int c = c0 + ty + j*8;
        t[ty + j*8][tx] = x[((size_t)b*Cv + c)*HWv + hw0 + tx];
    }
    __syncthreads();
    #pragma unroll
    for (int j = 0; j < 4; j++) {
        int hw = hw0 + ty + j*8;
        g_xt[((size_t)b*HWv + hw)*Cv + c0 + tx] = t[tx][ty + j*8];
    }
}

// ---------------------------------------------------------------------------
// fused offset(18ch) + mask(9ch), 32x8 tile, 128 threads, 2 px/thread
// (R4 configuration — measured best)
// ---------------------------------------------------------------------------
__global__ void __launch_bounds__(128, 3) offmask_kernel(
    const float* __restrict__ x,
    const float* __restrict__ bh, const float* __restrict__ bv,
    const float* __restrict__ bm)
{
    __shared__ float tiles[2][22*47];
    int b  = blockIdx.z;
    int h0 = blockIdx.y * 8;
    int wb = blockIdx.x * 32;
    int tid = threadIdx.x;
    int tx = tid & 15, ty = tid >> 4;
    int h = h0 + ty;
    int w = wb + 2*tx;

    int  soff[8], sidx[8];
    #pragma unroll
    for (int s = 0; s < 8; s++) {
        int i = tid + s*128;
        if (i < 22*46) {
            int r = i / 46, cc = i - r*46;
            int gh = h0 + r - 7, gw = wb + cc - 7;
            sidx[s] = r*47 + cc;
            soff[s] = (gh >= 0 && gh < Hv && gw >= 0 && gw < Wv) ? gh*Wv + gw : -1;
        } else { sidx[s] = -1; soff[s] = -1; }
    }

    float acc0[18], acc1[18], am0[9], am1[9];
    #pragma unroll
    for (int o = 0; o < 18; o++) { float bo = bh[o] + bv[o]; acc0[o] = bo; acc1[o] = bo; }
    #pragma unroll
    for (int o = 0; o < 9; o++)  { float bo = bm[o]; am0[o] = bo; am1[o] = bo; }

    const float* xb = x + (size_t)b*Cv*HWv;

    {
        const float* xc = xb;
        #pragma unroll
        for (int s = 0; s < 8; s++)
            if (sidx[s] >= 0) tiles[0][sidx[s]] = (soff[s] >= 0) ? __ldg(xc + soff[s]) : 0.f;
    }

    for (int c = 0; c < Cv; c++) {
        __syncthreads();
        if (c + 1 < Cv) {
            const float* xc = xb + (c+1)*HWv;
            float* dst = tiles[(c+1) & 1];
            #pragma unroll
            for (int s = 0; s < 8; s++)
                if (sidx[s] >= 0) dst[sidx[s]] = (soff[s] >= 0) ? __ldg(xc + soff[s]) : 0.f;
        }
        const float* tile = tiles[c & 1];

        float xr[16];
        #pragma unroll
        for (int i = 0; i < 16; i++) xr[i] = tile[(ty+7)*47 + 2*tx + i];
        float xcA[15], xcB[15];
        #pragma unroll
        for (int i = 0; i < 15; i++) {
            xcA[i] = tile[(ty+i)*47 + 2*tx + 7];
            xcB[i] = tile[(ty+i)*47 + 2*tx + 8];
        }
        float t00 = tile[(ty+6)*47 + 2*tx + 6];
        float t01 = tile[(ty+6)*47 + 2*tx + 9];
        float t10 = tile[(ty+8)*47 + 2*tx + 6];
        float t11 = tile[(ty+8)*47 + 2*tx + 9];

        const float4* whc = (const float4*)(g_whP + c*288);
        const float4* wvc = (const float4*)(g_wvP + c*288);
        const float4* wmc = (const float4*)(g_wmP + c*108);
        #pragma unroll
        for (int o = 0; o < 18; o++) {
            float4 q0 = whc[o*4+0], q1 = whc[o*4+1], q2 = whc[o*4+2], q3 = whc[o*4+3];
            float wkh[15] = {q0.x,q0.y,q0.z,q0.w, q1.x,q1.y,q1.z,q1.w,
                             q2.x,q2.y,q2.z,q2.w, q3.x,q3.y,q3.z};
            float a0 = acc0[o], a1 = acc1[o];
            #pragma unroll
            for (int k = 0; k < 15; k++) {
                a0 = fmaf(xr[k],   wkh[k], a0);
                a1 = fmaf(xr[k+1], wkh[k], a1);
            }
            float4 v0 = wvc[o*4+0], v1 = wvc[o*4+1], v2 = wvc[o*4+2], v3 = wvc[o*4+3];
            float wkv[15] = {v0.x,v0.y,v0.z,v0.w, v1.x,v1.y,v1.z,v1.w,
                             v2.x,v2.y,v2.z,v2.w, v3.x,v3.y,v3.z};
            #pragma unroll
            for (int k = 0; k < 15; k++) {
                a0 = fmaf(xcA[k], wkv[k], a0);
                a1 = fmaf(xcB[k], wkv[k], a1);
            }
            acc0[o] = a0; acc1[o] = a1;
        }
        #pragma unroll
        for (int o = 0; o < 9; o++) {
            float4 q0 = wmc[o*3], q1 = wmc[o*3+1], q2 = wmc[o*3+2];
            float m0 = am0[o], m1 = am1[o];
            m0 = fmaf(t00,    q0.x, m0);  m1 = fmaf(xcA[6], q0.x, m1);
            m0 = fmaf(xcA[6], q0.y, m0);  m1 = fmaf(xcB[6], q0.y, m1);
            m0 = fmaf(xcB[6], q0.z, m0);  m1 = fmaf(t01,    q0.z, m1);
            m0 = fmaf(xr[6],  q0.w, m0);  m1 = fmaf(xr[7],  q0.w, m1);
            m0 = fmaf(xr[7],  q1.x, m0);  m1 = fmaf(xr[8],  q1.x, m1);
            m0 = fmaf(xr[8],  q1.y, m0);  m1 = fmaf(xr[9],  q1.y, m1);
            m0 = fmaf(t10,    q1.z, m0);  m1 = fmaf(xcA[8], q1.z, m1);
            m0 = fmaf(xcA[8], q1.w, m0);  m1 = fmaf(xcB[8], q1.w, m1);
            m0 = fmaf(xcB[8], q2.x, m0);  m1 = fmaf(t11,    q2.x, m1);
            am0[o] = m0; am1[o] = m1;
        }
    }

    #pragma unroll
    for (int o = 0; o < 18; o++) {
        float2 v; v.x = acc0[o]; v.y = acc1[o];
        *(float2*)&g_offset[((b*18 + o)*Hv + h)*Wv + w] = v;
    }
    #pragma unroll
    for (int o = 0; o < 9; o++) {
        float2 v;
        v.x = 1.f/(1.f + __expf(-am0[o]));
        v.y = 1.f/(1.f + __expf(-am1[o]));
        *(float2*)&g_mask[((b*9 + o)*Hv + h)*Wv + w] = v;
    }
}

// ---------------------------------------------------------------------------
// deform: 512 threads/block (16 warps), 16-px tile, full weight matrix in smem
// stage C: og16 x pg4 x ks8, 4o x 4p accumulators, 18 f4-chunks per slice
// ---------------------------------------------------------------------------
#define SW_STRIDE 608
#define SW_FLOATS 38912
#define SS_STRIDE 580
#define RED_SLICE 1088             // floats per K-slice (272 f4, skewed rows)
#define OFF_SS   SW_FLOATS
#define OFF_RED  (OFF_SS + 16*SS_STRIDE)
#define OFF_SAY  (OFF_RED + 8*RED_SLICE)
#define OFF_SAX  (OFF_SAY + 144)
#define OFF_SAW  (OFF_SAX + 144)
#define SMEM_FLOATS (OFF_SAW + 576)     // 57760 floats = 231040 B

__device__ __forceinline__ int wrow_off(int o) {
    return o*SW_STRIDE + ((o >> 2) & 7)*4;   // 16B skew per o-group
}

__global__ void __launch_bounds__(512, 1) deform_kernel(float* __restrict__ out) {
    extern __shared__ float smem[];
    float* sw  = smem;
    float* ss  = smem + OFF_SS;
    float* red = smem + OFF_RED;
    int*  sAy  = (int*)(smem + OFF_SAY);
    int*  sAx  = (int*)(smem + OFF_SAX);
    float4* sAw = (float4*)(smem + OFF_SAW);
    int tid = threadIdx.x;

    // load weights with skewed row layout
    const float4* wt4 = (const float4*)g_wdT;
    for (int i = tid; i < 64*144; i += 512) {
        int o = i / 144, q = i - o*144;
        ((float4*)(sw + wrow_off(o)))[q] = wt4[i];
    }

    int h  = blockIdx.x >> 3;
    int w0 = (blockIdx.x & 7) << 4;

    // stage C mapping: o-group 16 x pixel-group 4 x K-slice 8
    int og = tid & 15;
    int pg = (tid >> 4) & 3;
    int ks = tid >> 6;             // 0..7, slice of 18 f4 (72 floats)
    const float4* w0p = (const float4*)(sw + wrow_off(og*4+0)) + ks*18;
    const float4* w1p = (const float4*)(sw + wrow_off(og*4+1)) + ks*18;
    const float4* w2p = (const float4*)(sw + wrow_off(og*4+2)) + ks*18;
    const float4* w3p = (const float4*)(sw + wrow_off(og*4+3)) + ks*18;
    const float4* p0p = (const float4*)(ss + (pg*4+0)*SS_STRIDE) + ks*18;
    const float4* p1p = (const float4*)(ss + (pg*4+1)*SS_STRIDE) + ks*18;
    const float4* p2p = (const float4*)(ss + (pg*4+2)*SS_STRIDE) + ks*18;
    const float4* p3p = (const float4*)(ss + (pg*4+3)*SS_STRIDE) + ks*18;

    for (int b = 0; b < Bv; b++) {
        __syncthreads();
        if (tid < 144) {
            int p = tid / 9, k = tid - p*9;
            int w = w0 + p;
            int ky = k / 3, kx = k - ky*3;
            float dy = g_offset[((b*18 + 2*k    )*Hv + h)*Wv + w];
            float dx = g_offset[((b*18 + 2*k + 1)*Hv + h)*Wv + w];
            float m  = g_mask  [((b*9  + k      )*Hv + h)*Wv + w];
            float py = (float)(h + ky - 1) + dy;
            float px = (float)(w + kx - 1) + dx;
            float y0f = floorf(py), x0f = floorf(px);
            float wy1 = py - y0f, wx1 = px - x0f;
            float wy0 = 1.f - wy1, wx0 = 1.f - wx1;
            int iy0 = (int)y0f, ix0 = (int)x0f;
            bool vy0 = (iy0 >= 0)  && (iy0 < Hv);
            bool vy1 = (iy0 >= -1) && (iy0 < Hv-1);
            bool vx0 = (ix0 >= 0)  && (ix0 < Wv);
            bool vx1 = (ix0 >= -1) && (ix0 < Wv-1);
            sAy[tid] = iy0; sAx[tid] = ix0;
            sAw[tid] = make_float4((vy0 && vx0) ? m*wy0*wx0 : 0.f,
                                   (vy0 && vx1) ? m*wy0*wx1 : 0.f,
                                   (vy1 && vx0) ? m*wy1*wx0 : 0.f,
                                   (vy1 && vx1) ? m*wy1*wx1 : 0.f);
        }
        __syncthreads();

        const float4* xb4 = (const float4*)g_xt + (size_t)b*HWv*16;
        #pragma unroll
        for (int itb = 0; itb < 5; itb++) {
            int it = itb*512 + tid;       // 0..2303
            if (it < 2304) {
                int pk = it >> 4, cq = it & 15;
                int iy0 = sAy[pk], ix0 = sAx[pk];
                float4 wg = sAw[pk];
                int y0c = min(Hv-1, max(0, iy0));
                int y1c = min(Hv-1, max(0, iy0 + 1));
                int x0c = min(Wv-1, max(0, ix0));
                int x1c = min(Wv-1, max(0, ix0 + 1));
                float4 v00 = xb4[(y0c*Wv + x0c)*16 + cq];
                float4 v01 = xb4[(y0c*Wv + x1c)*16 + cq];
                float4 v10 = xb4[(y1c*Wv + x0c)*16 + cq];
                float4 v11 = xb4[(y1c*Wv + x1c)*16 + cq];
                float4 r;
                r.x = fmaf(wg.w, v11.x, fmaf(wg.z, v10.x, fmaf(wg.y, v01.x, wg.x*v00.x)));
                r.y = fmaf(wg.w, v11.y, fmaf(wg.z, v10.y, fmaf(wg.y, v01.y, wg.x*v00.y)));
                r.z = fmaf(wg.w, v11.z, fmaf(wg.z, v10.z, fmaf(wg.y, v01.z, wg.x*v00.z)));
                r.w = fmaf(wg.w, v11.w, fmaf(wg.z, v10.w, fmaf(wg.y, v01.w, wg.x*v00.w)));
                int p = pk / 9, k = pk - p*9;
                ((float4*)(ss + p*SS_STRIDE))[k*16 + cq] = r;
            }
        }
        __syncthreads();

        // stage C: 16 accumulators (4 o x 4 p), 18 f4-chunks in this K-slice
        float a00=0,a01=0,a02=0,a03=0, a10=0,a11=0,a12=0,a13=0;
        float a20=0,a21=0,a22=0,a23=0, a30=0,a31=0,a32=0,a33=0;
        #pragma unroll
        for (int q = 0; q < 18; q++) {
            float4 qa = w0p[q], qb = w1p[q], qc = w2p[q], qd = w3p[q];
            float4 s0 = p0p[q], s1 = p1p[q], s2 = p2p[q], s3 = p3p[q];
            a00=fmaf(qa.x,s0.x,a00); a00=fmaf(qa.y,s0.y,a00); a00=fmaf(qa.z,s0.z,a00); a00=fmaf(qa.w,s0.w,a00);
            a01=fmaf(qa.x,s1.x,a01); a01=fmaf(qa.y,s1.y,a01); a01=fmaf(qa.z,s1.z,a01); a01=fmaf(qa.w,s1.w,a01);
            a02=fmaf(qa.x,s2.x,a02); a02=fmaf(qa.y,s2.y,a02); a02=fmaf(qa.z,s2.z,a02); a02=fmaf(qa.w,s2.w,a02);
            a03=fmaf(qa.x,s3.x,a03); a03=fmaf(qa.y,s3.y,a03); a03=fmaf(qa.z,s3.z,a03); a03=fmaf(qa.w,s3.w,a03);
            a10=fmaf(qb.x,s0.x,a10); a10=fmaf(qb.y,s0.y,a10); a10=fmaf(qb.z,s0.z,a10); a10=fmaf(qb.w,s0.w,a10);
            a11=fmaf(qb.x,s1.x,a11); a11=fmaf(qb.y,s1.y,a11); a11=fmaf(qb.z,s1.z,a11); a11=fmaf(qb.w,s1.w,a11);
            a12=fmaf(qb.x,s2.x,a12); a12=fmaf(qb.y,s2.y,a12); a12=fmaf(qb.z,s2.z,a12); a12=fmaf(qb.w,s2.w,a12);
            a13=fmaf(qb.x,s3.x,a13); a13=fmaf(qb.y,s3.y,a13); a13=fmaf(qb.z,s3.z,a13); a13=fmaf(qb.w,s3.w,a13);
            a20=fmaf(qc.x,s0.x,a20); a20=fmaf(qc.y,s0.y,a20); a20=fmaf(qc.z,s0.z,a20); a20=fmaf(qc.w,s0.w,a20);
            a21=fmaf(qc.x,s1.x,a21); a21=fmaf(qc.y,s1.y,a21); a21=fmaf(qc.z,s1.z,a21); a21=fmaf(qc.w,s1.w,a21);
            a22=fmaf(qc.x,s2.x,a22); a22=fmaf(qc.y,s2.y,a22); a22=fmaf(qc.z,s2.z,a22); a22=fmaf(qc.w,s2.w,a22);
            a23=fmaf(qc.x,s3.x,a23); a23=fmaf(qc.y,s3.y,a23); a23=fmaf(qc.z,s3.z,a23); a23=fmaf(qc.w,s3.w,a23);
            a30=fmaf(qd.x,s0.x,a30); a30=fmaf(qd.y,s0.y,a30); a30=fmaf(qd.z,s0.z,a30); a30=fmaf(qd.w,s0.w,a30);
            a31=fmaf(qd.x,s1.x,a31); a31=fmaf(qd.y,s1.y,a31); a31=fmaf(qd.z,s1.z,a31); a31=fmaf(qd.w,s1.w,a31);
            a32=fmaf(qd.x,s2.x,a32); a32=fmaf(qd.y,s2.y,a32); a32=fmaf(qd.z,s2.z,a32); a32=fmaf(qd.w,s2.w,a32);
            a33=fmaf(qd.x,s3.x,a33); a33=fmaf(qd.y,s3.y,a33); a33=fmaf(qd.z,s3.z,a33); a33=fmaf(qd.w,s3.w,a33);
        }
        // partial store: f4 idx = ks*272 + og*17 + oi*4 + pg  (skewed rows)
        {
            float4* rp = (float4*)red + ks*272 + og*17 + pg;
            rp[0]  = make_float4(a00,a01,a02,a03);
            rp[4]  = make_float4(a10,a11,a12,a13);
            rp[8]  = make_float4(a20,a21,a22,a23);
            rp[12] = make_float4(a30,a31,a32,a33);
        }
        __syncthreads();

        // reduce 8 K-slices: thread t<256 handles o = t>>2, pg = t&3
        if (tid < 256) {
            int o = tid >> 2, rpg = tid & 3;
            int base = (o >> 2)*17 + (o & 3)*4 + rpg;
            const float4* r4 = (const float4*)red;
            float4 v0 = r4[base];
            float4 v1 = r4[272  + base];
            float4 v2 = r4[544  + base];
            float4 v3 = r4[816  + base];
            float4 v4 = r4[1088 + base];
            float4 v5 = r4[1360 + base];
            float4 v6 = r4[1632 + base];
            float4 v7 = r4[1904 + base];
            float4 res;
            res.x = ((v0.x+v1.x)+(v2.x+v3.x)) + ((v4.x+v5.x)+(v6.x+v7.x));
            res.y = ((v0.y+v1.y)+(v2.y+v3.y)) + ((v4.y+v5.y)+(v6.y+v7.y));
            res.z = ((v0.z+v1.z)+(v2.z+v3.z)) + ((v4.z+v5.z)+(v6.z+v7.z));
            res.w = ((v0.w+v1.w)+(v2.w+v3.w)) + ((v4.w+v5.w)+(v6.w+v7.w));
            *(float4*)&out[((size_t)(b*Ov + o)*Hv + h)*Wv + w0 + rpg*4] = res;
        }
    }
}

// ---------------------------------------------------------------------------
// BN
// ---------------------------------------------------------------------------
__global__ void reduce_kernel(const float* __restrict__ y) {
    int c = blockIdx.x, b = blockIdx.y, tid = threadIdx.x;
    const float4* p = (const float4*)y + (size_t)(b*Ov + c)*4096;
    float s = 0.f, q = 0.f;
    for (int i = tid; i < 4096; i += 256) {
        float4 v = p[i];
        s += v.x + v.y + v.z + v.w;
        q = fmaf(v.x,v.x,q); q = fmaf(v.y,v.y,q); q = fmaf(v.z,v.z,q); q = fmaf(v.w,v.w,q);
    }
    __shared__ float ssum[8], ssq[8];
    #pragma unroll
    for (int o = 16; o > 0; o >>= 1) {
        s += __shfl_down_sync(0xffffffff, s, o);
        q += __shfl_down_sync(0xffffffff, q, o);
    }
    if ((tid & 31) == 0) { ssum[tid >> 5] = s; ssq[tid >> 5] = q; }
    __syncthreads();
    if (tid < 8) {
        s = ssum[tid]; q = ssq[tid];
        #pragma unroll
        for (int o = 4; o > 0; o >>= 1) {
            s += __shfl_down_sync(0xff, s, o);
            q += __shfl_down_sync(0xff, q, o);
        }
        if (tid == 0) { g_psum[c*Bv + b] = s; g_psq[c*Bv + b] = q; }
    }
}

__global__ void stats_kernel() {
    int c = threadIdx.x;
    float s = 0.f, q = 0.f;
    for (int b = 0; b < Bv; b++) { s += g_psum[c*Bv + b]; q += g_psq[c*Bv + b]; }
    const float inv = 1.f / (float)(Bv*HWv);
    float mean = s * inv;
    float var  = q * inv - mean*mean;
    g_mean[c] = mean;
    g_rstd[c] = rsqrtf(var + 1e-5f);
}

__global__ void bn_kernel(float* __restrict__ y,
                          const float* __restrict__ gamma,
                          const float* __restrict__ beta) {
    int idx = blockIdx.x*256 + threadIdx.x;
    if (idx >= Bv*Ov*HWv/4) return;
    int c = (idx >> 12) & 63;
    float a  = g_rstd[c] * gamma[c];
    float bb = fmaf(-g_mean[c], a, beta[c]);
    float4* p = (float4*)y;
    float4 v = p[idx];
    v.x = fmaxf(fmaf(v.x, a, bb), 0.f);
    v.y = fmaxf(fmaf(v.y, a, bb), 0.f);
    v.z = fmaxf(fmaf(v.z, a, bb), 0.f);
    v.w = fmaxf(fmaf(v.w, a, bb), 0.f);
    p[idx] = v;
}

// ---------------------------------------------------------------------------
extern "C" void kernel_launch(void* const* d_in, const int* in_sizes, int n_in,
                              void* d_out, int out_size) {
    const float* x     = (const float*)d_in[0];
    const float* wh    = (const float*)d_in[1];
    const float* bh    = (const float*)d_in[2];
    const float* wv    = (const float*)d_in[3];
    const float* bv    = (const float*)d_in[4];
    const float* wm    = (const float*)d_in[5];
    const float* bm    = (const float*)d_in[6];
    const float* wd    = (const float*)d_in[7];
    const float* gamma = (const float*)d_in[8];
    const float* beta  = (const float*)d_in[9];
    float* out = (float*)d_out;

    const int deform_smem = SMEM_FLOATS * 4;   // 231040 B
    cudaFuncSetAttribute(deform_kernel, cudaFuncAttributeMaxDynamicSharedMemorySize, deform_smem);

    pack_kernel<<<(18432 + 6912 + 36864 + 255)/256, 256>>>(wh, wv, wm, wd);
    transpose_kernel<<<dim3(HWv/32, Cv/32, Bv), dim3(32, 8)>>>(x);
    offmask_kernel<<<dim3(Wv/32, Hv/8, Bv), 128>>>(x, bh, bv, bm);
    deform_kernel<<<1024, 512, deform_smem>>>(out);
    reduce_kernel<<<dim3(Ov, Bv), 256>>>(out);
    stats_kernel<<<1, Ov>>>();
    bn_kernel<<<(Bv*Ov*HWv/4 + 255)/256, 256>>>(out, gamma, beta);
}

// round 7
// speedup vs baseline: 1.3028x; 1.0969x over previous
#include <cuda_runtime.h>
#include <math.h>

#define Bv 8
#define Cv 64
#define Hv 128
#define Wv 128
#define Ov 64
#define HWv (Hv*Wv)

// scratch (__device__ globals; no allocation allowed)
__device__ float g_offset[Bv*18*HWv];   // (B,18,H,W)
__device__ float g_mask[Bv*9*HWv];      // (B,9,H,W)
__device__ float g_xt[(size_t)Bv*HWv*Cv]; // (B,H,W,C)
__device__ float g_whP[Cv*18*16];
__device__ float g_wvP[Cv*18*16];
__device__ float g_wmP[Cv*9*12];
__device__ float g_wdT[Ov*576];         // [o][j], j = k*16 + c/4 (float4 granules)
__device__ float g_psum[Ov*Bv];
__device__ float g_psq[Ov*Bv];
__device__ float g_mean[Ov];
__device__ float g_rstd[Ov];

// ---------------------------------------------------------------------------
// weight packer
// ---------------------------------------------------------------------------
__global__ void pack_kernel(const float* __restrict__ wh, const float* __restrict__ wv,
                            const float* __restrict__ wm, const float* __restrict__ wd) {
    int idx = blockIdx.x*256 + threadIdx.x;
    if (idx < 18432) {
        int c = idx/288, r = idx - c*288, o = r >> 4, k = r & 15;
        g_whP[idx] = (k < 15) ? wh[(o*Cv + c)*15 + k] : 0.f;
        g_wvP[idx] = (k < 15) ? wv[(o*Cv + c)*15 + k] : 0.f;
    } else if (idx < 18432 + 6912) {
        int j = idx - 18432;
        int c = j/108, r = j - c*108, o = r/12, k = r - o*12;
        g_wmP[j] = (k < 9) ? wm[(o*Cv + c)*9 + k] : 0.f;
    } else if (idx < 18432 + 6912 + 36864) {
        int j = idx - 18432 - 6912;
        int o = j/576, r = j - o*576, k = r >> 6, c = r & 63;
        g_wdT[j] = wd[(o*Cv + c)*9 + k];
    }
}

// ---------------------------------------------------------------------------
// x (B,C,HW) -> xt (B,HW,C)
// ---------------------------------------------------------------------------
__global__ void transpose_kernel(const float* __restrict__ x) {
    __shared__ float t[32][33];
    int b = blockIdx.z;
    int hw0 = blockIdx.x * 32;
    int c0  = blockIdx.y * 32;
    int tx = threadIdx.x, ty = threadIdx.y;
    #pragma unroll
    for (int j = 0; j < 4; j++) {
        int c = c0 + ty + j*8;
        t[ty + j*8][tx] = x[((size_t)b*Cv + c)*HWv + hw0 + tx];
    }
    __syncthreads();
    #pragma unroll
    for (int j = 0; j < 4; j++) {
        int hw = hw0 + ty + j*8;
        g_xt[((size_t)b*HWv + hw)*Cv + c0 + tx] = t[tx][ty + j*8];
    }
}

// ---------------------------------------------------------------------------
// fused offset(18ch) + mask(9ch), 32x8 tile, 128 threads, 2 px/thread
// occupancy 4 -> 592 concurrent blocks >= 512 grid (single wave)
// ---------------------------------------------------------------------------
__global__ void __launch_bounds__(128, 4) offmask_kernel(
    const float* __restrict__ x,
    const float* __restrict__ bh, const float* __restrict__ bv,
    const float* __restrict__ bm)
{
    __shared__ float tiles[2][22*47];
    int b  = blockIdx.z;
    int h0 = blockIdx.y * 8;
    int wb = blockIdx.x * 32;
    int tid = threadIdx.x;
    int tx = tid & 15, ty = tid >> 4;
    int h = h0 + ty;
    int w = wb + 2*tx;

    int  soff[8], sidx[8];
    #pragma unroll
    for (int s = 0; s < 8; s++) {
        int i = tid + s*128;
        if (i < 22*46) {
            int r = i / 46, cc = i - r*46;
            int gh = h0 + r - 7, gw = wb + cc - 7;
            sidx[s] = r*47 + cc;
            soff[s] = (gh >= 0 && gh < Hv && gw >= 0 && gw < Wv) ? gh*Wv + gw : -1;
        } else { sidx[s] = -1; soff[s] = -1; }
    }

    float acc0[18], acc1[18], am0[9], am1[9];
    #pragma unroll
    for (int o = 0; o < 18; o++) { float bo = bh[o] + bv[o]; acc0[o] = bo; acc1[o] = bo; }
    #pragma unroll
    for (int o = 0; o < 9; o++)  { float bo = bm[o]; am0[o] = bo; am1[o] = bo; }

    const float* xb = x + (size_t)b*Cv*HWv;

    {
        const float* xc = xb;
        #pragma unroll
        for (int s = 0; s < 8; s++)
            if (sidx[s] >= 0) tiles[0][sidx[s]] = (soff[s] >= 0) ? __ldg(xc + soff[s]) : 0.f;
    }

    for (int c = 0; c < Cv; c++) {
        __syncthreads();
        if (c + 1 < Cv) {
            const float* xc = xb + (c+1)*HWv;
            float* dst = tiles[(c+1) & 1];
            #pragma unroll
            for (int s = 0; s < 8; s++)
                if (sidx[s] >= 0) dst[sidx[s]] = (soff[s] >= 0) ? __ldg(xc + soff[s]) : 0.f;
        }
        const float* tile = tiles[c & 1];

        float xr[16];
        #pragma unroll
        for (int i = 0; i < 16; i++) xr[i] = tile[(ty+7)*47 + 2*tx + i];
        float xcA[15], xcB[15];
        #pragma unroll
        for (int i = 0; i < 15; i++) {
            xcA[i] = tile[(ty+i)*47 + 2*tx + 7];
            xcB[i] = tile[(ty+i)*47 + 2*tx + 8];
        }
        float t00 = tile[(ty+6)*47 + 2*tx + 6];
        float t01 = tile[(ty+6)*47 + 2*tx + 9];
        float t10 = tile[(ty+8)*47 + 2*tx + 6];
        float t11 = tile[(ty+8)*47 + 2*tx + 9];

        const float4* whc = (const float4*)(g_whP + c*288);
        const float4* wvc = (const float4*)(g_wvP + c*288);
        const float4* wmc = (const float4*)(g_wmP + c*108);
        #pragma unroll
        for (int o = 0; o < 18; o++) {
            float4 q0 = whc[o*4+0], q1 = whc[o*4+1], q2 = whc[o*4+2], q3 = whc[o*4+3];
            float wkh[15] = {q0.x,q0.y,q0.z,q0.w, q1.x,q1.y,q1.z,q1.w,
                             q2.x,q2.y,q2.z,q2.w, q3.x,q3.y,q3.z};
            float a0 = acc0[o], a1 = acc1[o];
            #pragma unroll
            for (int k = 0; k < 15; k++) {
                a0 = fmaf(xr[k],   wkh[k], a0);
                a1 = fmaf(xr[k+1], wkh[k], a1);
            }
            float4 v0 = wvc[o*4+0], v1 = wvc[o*4+1], v2 = wvc[o*4+2], v3 = wvc[o*4+3];
            float wkv[15] = {v0.x,v0.y,v0.z,v0.w, v1.x,v1.y,v1.z,v1.w,
                             v2.x,v2.y,v2.z,v2.w, v3.x,v3.y,v3.z};
            #pragma unroll
            for (int k = 0; k < 15; k++) {
                a0 = fmaf(xcA[k], wkv[k], a0);
                a1 = fmaf(xcB[k], wkv[k], a1);
            }
            acc0[o] = a0; acc1[o] = a1;
        }
        #pragma unroll
        for (int o = 0; o < 9; o++) {
            float4 q0 = wmc[o*3], q1 = wmc[o*3+1], q2 = wmc[o*3+2];
            float m0 = am0[o], m1 = am1[o];
            m0 = fmaf(t00,    q0.x, m0);  m1 = fmaf(xcA[6], q0.x, m1);
            m0 = fmaf(xcA[6], q0.y, m0);  m1 = fmaf(xcB[6], q0.y, m1);
            m0 = fmaf(xcB[6], q0.z, m0);  m1 = fmaf(t01,    q0.z, m1);
            m0 = fmaf(xr[6],  q0.w, m0);  m1 = fmaf(xr[7],  q0.w, m1);
            m0 = fmaf(xr[7],  q1.x, m0);  m1 = fmaf(xr[8],  q1.x, m1);
            m0 = fmaf(xr[8],  q1.y, m0);  m1 = fmaf(xr[9],  q1.y, m1);
            m0 = fmaf(t10,    q1.z, m0);  m1 = fmaf(xcA[8], q1.z, m1);
            m0 = fmaf(xcA[8], q1.w, m0);  m1 = fmaf(xcB[8], q1.w, m1);
            m0 = fmaf(xcB[8], q2.x, m0);  m1 = fmaf(t11,    q2.x, m1);
            am0[o] = m0; am1[o] = m1;
        }
    }

    #pragma unroll
    for (int o = 0; o < 18; o++) {
        float2 v; v.x = acc0[o]; v.y = acc1[o];
        *(float2*)&g_offset[((b*18 + o)*Hv + h)*Wv + w] = v;
    }
    #pragma unroll
    for (int o = 0; o < 9; o++) {
        float2 v;
        v.x = 1.f/(1.f + __expf(-am0[o]));
        v.y = 1.f/(1.f + __expf(-am1[o]));
        *(float2*)&g_mask[((b*9 + o)*Hv + h)*Wv + w] = v;
    }
}

// ---------------------------------------------------------------------------
// deform: 512 threads, 16-px tile, weights resident in smem
// stage C: warp = o-group (4 o), lane = ks(16) x pg(2); thread = 4o x 8p,
// K-slice = 36 floats; shfl_xor reduction over ks; no smem reduction
// ---------------------------------------------------------------------------
#define SW_STRIDE 608
#define SW_FLOATS 38912
#define SS_STRIDE 580
#define OFF_SS   SW_FLOATS
#define OFF_SAY  (OFF_SS + 16*SS_STRIDE)
#define OFF_SAX  (OFF_SAY + 144)
#define OFF_SAW  (OFF_SAX + 144)
#define SMEM_FLOATS (OFF_SAW + 576)     // 49056 floats = 196224 B

__device__ __forceinline__ int wrow_off(int o) {
    return o*SW_STRIDE + ((o >> 2) & 7)*4;
}

__global__ void __launch_bounds__(512, 1) deform_kernel(float* __restrict__ out) {
    extern __shared__ float smem[];
    float* sw  = smem;
    float* ss  = smem + OFF_SS;
    int*  sAy  = (int*)(smem + OFF_SAY);
    int*  sAx  = (int*)(smem + OFF_SAX);
    float4* sAw = (float4*)(smem + OFF_SAW);
    int tid = threadIdx.x;

    const float4* wt4 = (const float4*)g_wdT;
    for (int i = tid; i < 64*144; i += 512) {
        int o = i / 144, q = i - o*144;
        ((float4*)(sw + wrow_off(o)))[q] = wt4[i];
    }

    int h  = blockIdx.x >> 3;
    int w0 = (blockIdx.x & 7) << 4;

    // stage C mapping
    int lane = tid & 31;
    int og   = tid >> 5;          // warp id = o-group, o = og*4 + oi
    int ks   = lane >> 1;         // K slice 0..15 (36 floats = 9 f4)
    int pg   = lane & 1;          // pixel group: p = pg*8 + j
    const float4* wq0 = (const float4*)(sw + wrow_off(og*4+0)) + ks*9;
    const float4* wq1 = (const float4*)(sw + wrow_off(og*4+1)) + ks*9;
    const float4* wq2 = (const float4*)(sw + wrow_off(og*4+2)) + ks*9;
    const float4* wq3 = (const float4*)(sw + wrow_off(og*4+3)) + ks*9;
    const float4* pr[8];
    #pragma unroll
    for (int j = 0; j < 8; j++)
        pr[j] = (const float4*)(ss + (pg*8 + j)*SS_STRIDE) + ks*9;

    for (int b = 0; b < Bv; b++) {
        __syncthreads();   // ss reads done (stage C) / weights ready
        if (tid < 144) {
            int p = tid / 9, k = tid - p*9;
            int w = w0 + p;
            int ky = k / 3, kx = k - ky*3;
            float dy = g_offset[((b*18 + 2*k    )*Hv + h)*Wv + w];
            float dx = g_offset[((b*18 + 2*k + 1)*Hv + h)*Wv + w];
            float m  = g_mask  [((b*9  + k      )*Hv + h)*Wv + w];
            float py = (float)(h + ky - 1) + dy;
            float px = (float)(w + kx - 1) + dx;
            float y0f = floorf(py), x0f = floorf(px);
            float wy1 = py - y0f, wx1 = px - x0f;
            float wy0 = 1.f - wy1, wx0 = 1.f - wx1;
            int iy0 = (int)y0f, ix0 = (int)x0f;
            bool vy0 = (iy0 >= 0)  && (iy0 < Hv);
            bool vy1 = (iy0 >= -1) && (iy0 < Hv-1);
            bool vx0 = (ix0 >= 0)  && (ix0 < Wv);
            bool vx1 = (ix0 >= -1) && (ix0 < Wv-1);
            sAy[tid] = iy0; sAx[tid] = ix0;
            sAw[tid] = make_float4((vy0 && vx0) ? m*wy0*wx0 : 0.f,
                                   (vy0 && vx1) ? m*wy0*wx1 : 0.f,
                                   (vy1 && vx0) ? m*wy1*wx0 : 0.f,
                                   (vy1 && vx1) ? m*wy1*wx1 : 0.f);
        }
        __syncthreads();

        const float4* xb4 = (const float4*)g_xt + (size_t)b*HWv*16;
        #pragma unroll
        for (int itb = 0; itb < 5; itb++) {
            int it = itb*512 + tid;       // 0..2303
            if (it < 2304) {
                int pk = it >> 4, cq = it & 15;
                int iy0 = sAy[pk], ix0 = sAx[pk];
                float4 wg = sAw[pk];
                int y0c = min(Hv-1, max(0, iy0));
                int y1c = min(Hv-1, max(0, iy0 + 1));
                int x0c = min(Wv-1, max(0, ix0));
                int x1c = min(Wv-1, max(0, ix0 + 1));
                float4 v00 = xb4[(y0c*Wv + x0c)*16 + cq];
                float4 v01 = xb4[(y0c*Wv + x1c)*16 + cq];
                float4 v10 = xb4[(y1c*Wv + x0c)*16 + cq];
                float4 v11 = xb4[(y1c*Wv + x1c)*16 + cq];
                float4 r;
                r.x = fmaf(wg.w, v11.x, fmaf(wg.z, v10.x, fmaf(wg.y, v01.x, wg.x*v00.x)));
                r.y = fmaf(wg.w, v11.y, fmaf(wg.z, v10.y, fmaf(wg.y, v01.y, wg.x*v00.y)));
                r.z = fmaf(wg.w, v11.z, fmaf(wg.z, v10.z, fmaf(wg.y, v01.z, wg.x*v00.z)));
                r.w = fmaf(wg.w, v11.w, fmaf(wg.z, v10.w, fmaf(wg.y, v01.w, wg.x*v00.w)));
                int p = pk / 9, k = pk - p*9;
                ((float4*)(ss + p*SS_STRIDE))[k*16 + cq] = r;
            }
        }
        __syncthreads();

        // stage C: 32 accumulators (4 o x 8 p), 9 f4-chunks in this K-slice
        float a0[8], a1[8], a2[8], a3[8];
        #pragma unroll
        for (int j = 0; j < 8; j++) { a0[j]=0.f; a1[j]=0.f; a2[j]=0.f; a3[j]=0.f; }
        #pragma unroll
        for (int q = 0; q < 9; q++) {
            float4 qa = wq0[q], qb = wq1[q], qc = wq2[q], qd = wq3[q];
            #pragma unroll
            for (int j = 0; j < 8; j++) {
                float4 s = pr[j][q];
                a0[j]=fmaf(qa.x,s.x,a0[j]); a0[j]=fmaf(qa.y,s.y,a0[j]); a0[j]=fmaf(qa.z,s.z,a0[j]); a0[j]=fmaf(qa.w,s.w,a0[j]);
                a1[j]=fmaf(qb.x,s.x,a1[j]); a1[j]=fmaf(qb.y,s.y,a1[j]); a1[j]=fmaf(qb.z,s.z,a1[j]); a1[j]=fmaf(qb.w,s.w,a1[j]);
                a2[j]=fmaf(qc.x,s.x,a2[j]); a2[j]=fmaf(qc.y,s.y,a2[j]); a2[j]=fmaf(qc.z,s.z,a2[j]); a2[j]=fmaf(qc.w,s.w,a2[j]);
                a3[j]=fmaf(qd.x,s.x,a3[j]); a3[j]=fmaf(qd.y,s.y,a3[j]); a3[j]=fmaf(qd.z,s.z,a3[j]); a3[j]=fmaf(qd.w,s.w,a3[j]);
            }
        }
        // shfl reduction over ks (lane bits 1..4)
        #pragma unroll
        for (int m = 2; m <= 16; m <<= 1) {
            #pragma unroll
            for (int j = 0; j < 8; j++) {
                a0[j] += __shfl_xor_sync(0xffffffff, a0[j], m);
                a1[j] += __shfl_xor_sync(0xffffffff, a1[j], m);
                a2[j] += __shfl_xor_sync(0xffffffff, a2[j], m);
                a3[j] += __shfl_xor_sync(0xffffffff, a3[j], m);
            }
        }
        if (lane < 2) {          // lane 0: px 0..7, lane 1: px 8..15
            size_t base = ((size_t)(b*Ov + og*4)*Hv + h)*Wv + w0 + pg*8;
            *(float4*)&out[base]            = make_float4(a0[0],a0[1],a0[2],a0[3]);
            *(float4*)&out[base + 4]        = make_float4(a0[4],a0[5],a0[6],a0[7]);
            *(float4*)&out[base + HWv]      = make_float4(a1[0],a1[1],a1[2],a1[3]);
            *(float4*)&out[base + HWv + 4]  = make_float4(a1[4],a1[5],a1[6],a1[7]);
            *(float4*)&out[base + 2*HWv]    = make_float4(a2[0],a2[1],a2[2],a2[3]);
            *(float4*)&out[base + 2*HWv+4]  = make_float4(a2[4],a2[5],a2[6],a2[7]);
            *(float4*)&out[base + 3*HWv]    = make_float4(a3[0],a3[1],a3[2],a3[3]);
            *(float4*)&out[base + 3*HWv+4]  = make_float4(a3[4],a3[5],a3[6],a3[7]);
        }
    }
}

// ---------------------------------------------------------------------------
// BN
// ---------------------------------------------------------------------------
__global__ void reduce_kernel(const float* __restrict__ y) {
    int c = blockIdx.x, b = blockIdx.y, tid = threadIdx.x;
    const float4* p = (const float4*)y + (size_t)(b*Ov + c)*4096;
    float s = 0.f, q = 0.f;
    for (int i = tid; i < 4096; i += 256) {
        float4 v = p[i];
        s += v.x + v.y + v.z + v.w;
        q = fmaf(v.x,v.x,q); q = fmaf(v.y,v.y,q); q = fmaf(v.z,v.z,q); q = fmaf(v.w,v.w,q);
    }
    __shared__ float ssum[8], ssq[8];
    #pragma unroll
    for (int o = 16; o > 0; o >>= 1) {
        s += __shfl_down_sync(0xffffffff, s, o);
        q += __shfl_down_sync(0xffffffff, q, o);
    }
    if ((tid & 31) == 0) { ssum[tid >> 5] = s; ssq[tid >> 5] = q; }
    __syncthreads();
    if (tid < 8) {
        s = ssum[tid]; q = ssq[tid];
        #pragma unroll
        for (int o = 4; o > 0; o >>= 1) {
            s += __shfl_down_sync(0xff, s, o);
            q += __shfl_down_sync(0xff, q, o);
        }
        if (tid == 0) { g_psum[c*Bv + b] = s; g_psq[c*Bv + b] = q; }
    }
}

__global__ void stats_kernel() {
    int c = threadIdx.x;
    float s = 0.f, q = 0.f;
    for (int b = 0; b < Bv; b++) { s += g_psum[c*Bv + b]; q += g_psq[c*Bv + b]; }
    const float inv = 1.f / (float)(Bv*HWv);
    float mean = s * inv;
    float var  = q * inv - mean*mean;
    g_mean[c] = mean;
    g_rstd[c] = rsqrtf(var + 1e-5f);
}

__global__ void bn_kernel(float* __restrict__ y,
                          const float* __restrict__ gamma,
                          const float* __restrict__ beta) {
    int idx = blockIdx.x*256 + threadIdx.x;
    if (idx >= Bv*Ov*HWv/4) return;
    int c = (idx >> 12) & 63;
    float a  = g_rstd[c] * gamma[c];
    float bb = fmaf(-g_mean[c], a, beta[c]);
    float4* p = (float4*)y;
    float4 v = p[idx];
    v.x = fmaxf(fmaf(v.x, a, bb), 0.f);
    v.y = fmaxf(fmaf(v.y, a, bb), 0.f);
    v.z = fmaxf(fmaf(v.z, a, bb), 0.f);
    v.w = fmaxf(fmaf(v.w, a, bb), 0.f);
    p[idx] = v;
}

// ---------------------------------------------------------------------------
extern "C" void kernel_launch(void* const* d_in, const int* in_sizes, int n_in,
                              void* d_out, int out_size) {
    const float* x     = (const float*)d_in[0];
    const float* wh    = (const float*)d_in[1];
    const float* bh    = (const float*)d_in[2];
    const float* wv    = (const float*)d_in[3];
    const float* bv    = (const float*)d_in[4];
    const float* wm    = (const float*)d_in[5];
    const float* bm    = (const float*)d_in[6];
    const float* wd    = (const float*)d_in[7];
    const float* gamma = (const float*)d_in[8];
    const float* beta  = (const float*)d_in[9];
    float* out = (float*)d_out;

    const int deform_smem = SMEM_FLOATS * 4;   // 196224 B
    cudaFuncSetAttribute(deform_kernel, cudaFuncAttributeMaxDynamicSharedMemorySize, deform_smem);

    pack_kernel<<<(18432 + 6912 + 36864 + 255)/256, 256>>>(wh, wv, wm, wd);
    transpose_kernel<<<dim3(HWv/32, Cv/32, Bv), dim3(32, 8)>>>(x);
    offmask_kernel<<<dim3(Wv/32, Hv/8, Bv), 128>>>(x, bh, bv, bm);
    deform_kernel<<<1024, 512, deform_smem>>>(out);
    reduce_kernel<<<dim3(Ov, Bv), 256>>>(out);
    stats_kernel<<<1, Ov>>>();
    bn_kernel<<<(Bv*Ov*HWv/4 + 255)/256, 256>>>(out, gamma, beta);
}

// round 8
// speedup vs baseline: 1.5003x; 1.1516x over previous
#include <cuda_runtime.h>
#include <math.h>

#define Bv 8
#define Cv 64
#define Hv 128
#define Wv 128
#define Ov 64
#define HWv (Hv*Wv)

// scratch (__device__ globals; no allocation allowed)
__device__ float g_offset[Bv*18*HWv];   // (B,18,H,W)
__device__ float g_mask[Bv*9*HWv];      // (B,9,H,W)
__device__ float g_xt[(size_t)Bv*HWv*Cv]; // (B,H,W,C)
__device__ float g_whP[Cv*18*16];
__device__ float g_wvP[Cv*18*16];
__device__ float g_wmP[Cv*9*12];
__device__ float g_wdT[Ov*576];         // [o][j], j = k*16 + c/4 (float4 granules)
__device__ float g_psum[Ov*Bv];
__device__ float g_psq[Ov*Bv];
__device__ float g_mean[Ov];
__device__ float g_rstd[Ov];

// ---------------------------------------------------------------------------
// weight packer
// ---------------------------------------------------------------------------
__global__ void pack_kernel(const float* __restrict__ wh, const float* __restrict__ wv,
                            const float* __restrict__ wm, const float* __restrict__ wd) {
    int idx = blockIdx.x*256 + threadIdx.x;
    if (idx < 18432) {
        int c = idx/288, r = idx - c*288, o = r >> 4, k = r & 15;
        g_whP[idx] = (k < 15) ? wh[(o*Cv + c)*15 + k] : 0.f;
        g_wvP[idx] = (k < 15) ? wv[(o*Cv + c)*15 + k] : 0.f;
    } else if (idx < 18432 + 6912) {
        int j = idx - 18432;
        int c = j/108, r = j - c*108, o = r/12, k = r - o*12;
        g_wmP[j] = (k < 9) ? wm[(o*Cv + c)*9 + k] : 0.f;
    } else if (idx < 18432 + 6912 + 36864) {
        int j = idx - 18432 - 6912;
        int o = j/576, r = j - o*576, k = r >> 6, c = r & 63;
        g_wdT[j] = wd[(o*Cv + c)*9 + k];
    }
}

// ---------------------------------------------------------------------------
// x (B,C,HW) -> xt (B,HW,C)
// ---------------------------------------------------------------------------
__global__ void transpose_kernel(const float* __restrict__ x) {
    __shared__ float t[32][33];
    int b = blockIdx.z;
    int hw0 = blockIdx.x * 32;
    int c0  = blockIdx.y * 32;
    int tx = threadIdx.x, ty = threadIdx.y;
    #pragma unroll
    for (int j = 0; j < 4; j++) {
        int c = c0 + ty + j*8;
        t[ty + j*8][tx] = x[((size_t)b*Cv + c)*HWv + hw0 + tx];
    }
    __syncthreads();
    #pragma unroll
    for (int j = 0; j < 4; j++) {
        int hw = hw0 + ty + j*8;
        g_xt[((size_t)b*HWv + hw)*Cv + c0 + tx] = t[tx][ty + j*8];
    }
}

// ---------------------------------------------------------------------------
// fused offset(18ch) + mask(9ch), 32x8 tile, 128 threads, 2 px/thread
// occupancy 4 -> single wave (measured win in R7)
// ---------------------------------------------------------------------------
__global__ void __launch_bounds__(128, 4) offmask_kernel(
    const float* __restrict__ x,
    const float* __restrict__ bh, const float* __restrict__ bv,
    const float* __restrict__ bm)
{
    __shared__ float tiles[2][22*47];
    int b  = blockIdx.z;
    int h0 = blockIdx.y * 8;
    int wb = blockIdx.x * 32;
    int tid = threadIdx.x;
    int tx = tid & 15, ty = tid >> 4;
    int h = h0 + ty;
    int w = wb + 2*tx;

    int  soff[8], sidx[8];
    #pragma unroll
    for (int s = 0; s < 8; s++) {
        int i = tid + s*128;
        if (i < 22*46) {
            int r = i / 46, cc = i - r*46;
            int gh = h0 + r - 7, gw = wb + cc - 7;
            sidx[s] = r*47 + cc;
            soff[s] = (gh >= 0 && gh < Hv && gw >= 0 && gw < Wv) ? gh*Wv + gw : -1;
        } else { sidx[s] = -1; soff[s] = -1; }
    }

    float acc0[18], acc1[18], am0[9], am1[9];
    #pragma unroll
    for (int o = 0; o < 18; o++) { float bo = bh[o] + bv[o]; acc0[o] = bo; acc1[o] = bo; }
    #pragma unroll
    for (int o = 0; o < 9; o++)  { float bo = bm[o]; am0[o] = bo; am1[o] = bo; }

    const float* xb = x + (size_t)b*Cv*HWv;

    {
        const float* xc = xb;
        #pragma unroll
        for (int s = 0; s < 8; s++)
            if (sidx[s] >= 0) tiles[0][sidx[s]] = (soff[s] >= 0) ? __ldg(xc + soff[s]) : 0.f;
    }

    for (int c = 0; c < Cv; c++) {
        __syncthreads();
        if (c + 1 < Cv) {
            const float* xc = xb + (c+1)*HWv;
            float* dst = tiles[(c+1) & 1];
            #pragma unroll
            for (int s = 0; s < 8; s++)
                if (sidx[s] >= 0) dst[sidx[s]] = (soff[s] >= 0) ? __ldg(xc + soff[s]) : 0.f;
        }
        const float* tile = tiles[c & 1];

        float xr[16];
        #pragma unroll
        for (int i = 0; i < 16; i++) xr[i] = tile[(ty+7)*47 + 2*tx + i];
        float xcA[15], xcB[15];
        #pragma unroll
        for (int i = 0; i < 15; i++) {
            xcA[i] = tile[(ty+i)*47 + 2*tx + 7];
            xcB[i] = tile[(ty+i)*47 + 2*tx + 8];
        }
        float t00 = tile[(ty+6)*47 + 2*tx + 6];
        float t01 = tile[(ty+6)*47 + 2*tx + 9];
        float t10 = tile[(ty+8)*47 + 2*tx + 6];
        float t11 = tile[(ty+8)*47 + 2*tx + 9];

        const float4* whc = (const float4*)(g_whP + c*288);
        const float4* wvc = (const float4*)(g_wvP + c*288);
        const float4* wmc = (const float4*)(g_wmP + c*108);
        #pragma unroll
        for (int o = 0; o < 18; o++) {
            float4 q0 = whc[o*4+0], q1 = whc[o*4+1], q2 = whc[o*4+2], q3 = whc[o*4+3];
            float wkh[15] = {q0.x,q0.y,q0.z,q0.w, q1.x,q1.y,q1.z,q1.w,
                             q2.x,q2.y,q2.z,q2.w, q3.x,q3.y,q3.z};
            float a0 = acc0[o], a1 = acc1[o];
            #pragma unroll
            for (int k = 0; k < 15; k++) {
                a0 = fmaf(xr[k],   wkh[k], a0);
                a1 = fmaf(xr[k+1], wkh[k], a1);
            }
            float4 v0 = wvc[o*4+0], v1 = wvc[o*4+1], v2 = wvc[o*4+2], v3 = wvc[o*4+3];
            float wkv[15] = {v0.x,v0.y,v0.z,v0.w, v1.x,v1.y,v1.z,v1.w,
                             v2.x,v2.y,v2.z,v2.w, v3.x,v3.y,v3.z};
            #pragma unroll
            for (int k = 0; k < 15; k++) {
                a0 = fmaf(xcA[k], wkv[k], a0);
                a1 = fmaf(xcB[k], wkv[k], a1);
            }
            acc0[o] = a0; acc1[o] = a1;
        }
        #pragma unroll
        for (int o = 0; o < 9; o++) {
            float4 q0 = wmc[o*3], q1 = wmc[o*3+1], q2 = wmc[o*3+2];
            float m0 = am0[o], m1 = am1[o];
            m0 = fmaf(t00,    q0.x, m0);  m1 = fmaf(xcA[6], q0.x, m1);
            m0 = fmaf(xcA[6], q0.y, m0);  m1 = fmaf(xcB[6], q0.y, m1);
            m0 = fmaf(xcB[6], q0.z, m0);  m1 = fmaf(t01,    q0.z, m1);
            m0 = fmaf(xr[6],  q0.w, m0);  m1 = fmaf(xr[7],  q0.w, m1);
            m0 = fmaf(xr[7],  q1.x, m0);  m1 = fmaf(xr[8],  q1.x, m1);
            m0 = fmaf(xr[8],  q1.y, m0);  m1 = fmaf(xr[9],  q1.y, m1);
            m0 = fmaf(t10,    q1.z, m0);  m1 = fmaf(xcA[8], q1.z, m1);
            m0 = fmaf(xcA[8], q1.w, m0);  m1 = fmaf(xcB[8], q1.w, m1);
            m0 = fmaf(xcB[8], q2.x, m0);  m1 = fmaf(t11,    q2.x, m1);
            am0[o] = m0; am1[o] = m1;
        }
    }

    #pragma unroll
    for (int o = 0; o < 18; o++) {
        float2 v; v.x = acc0[o]; v.y = acc1[o];
        *(float2*)&g_offset[((b*18 + o)*Hv + h)*Wv + w] = v;
    }
    #pragma unroll
    for (int o = 0; o < 9; o++) {
        float2 v;
        v.x = 1.f/(1.f + __expf(-am0[o]));
        v.y = 1.f/(1.f + __expf(-am1[o]));
        *(float2*)&g_mask[((b*9 + o)*Hv + h)*Wv + w] = v;
    }
}

// ---------------------------------------------------------------------------
// deform (exact R6 version — measured 420us): 512 threads, 16-px tile,
// stage C og16 x pg4 x ks8, smem reduction
// ---------------------------------------------------------------------------
#define SW_STRIDE 608
#define SW_FLOATS 38912
#define SS_STRIDE 580
#define RED_SLICE 1088
#define OFF_SS   SW_FLOATS
#define OFF_RED  (OFF_SS + 16*SS_STRIDE)
#define OFF_SAY  (OFF_RED + 8*RED_SLICE)
#define OFF_SAX  (OFF_SAY + 144)
#define OFF_SAW  (OFF_SAX + 144)
#define SMEM_FLOATS (OFF_SAW + 576)     // 57760 floats = 231040 B

__device__ __forceinline__ int wrow_off(int o) {
    return o*SW_STRIDE + ((o >> 2) & 7)*4;
}

__global__ void __launch_bounds__(512, 1) deform_kernel(float* __restrict__ out) {
    extern __shared__ float smem[];
    float* sw  = smem;
    float* ss  = smem + OFF_SS;
    float* red = smem + OFF_RED;
    int*  sAy  = (int*)(smem + OFF_SAY);
    int*  sAx  = (int*)(smem + OFF_SAX);
    float4* sAw = (float4*)(smem + OFF_SAW);
    int tid = threadIdx.x;

    const float4* wt4 = (const float4*)g_wdT;
    for (int i = tid; i < 64*144; i += 512) {
        int o = i / 144, q = i - o*144;
        ((float4*)(sw + wrow_off(o)))[q] = wt4[i];
    }

    int h  = blockIdx.x >> 3;
    int w0 = (blockIdx.x & 7) << 4;

    int og = tid & 15;
    int pg = (tid >> 4) & 3;
    int ks = tid >> 6;
    const float4* w0p = (const float4*)(sw + wrow_off(og*4+0)) + ks*18;
    const float4* w1p = (const float4*)(sw + wrow_off(og*4+1)) + ks*18;
    const float4* w2p = (const float4*)(sw + wrow_off(og*4+2)) + ks*18;
    const float4* w3p = (const float4*)(sw + wrow_off(og*4+3)) + ks*18;
    const float4* p0p = (const float4*)(ss + (pg*4+0)*SS_STRIDE) + ks*18;
    const float4* p1p = (const float4*)(ss + (pg*4+1)*SS_STRIDE) + ks*18;
    const float4* p2p = (const float4*)(ss + (pg*4+2)*SS_STRIDE) + ks*18;
    const float4* p3p = (const float4*)(ss + (pg*4+3)*SS_STRIDE) + ks*18;

    for (int b = 0; b < Bv; b++) {
        __syncthreads();
        if (tid < 144) {
            int p = tid / 9, k = tid - p*9;
            int w = w0 + p;
            int ky = k / 3, kx = k - ky*3;
            float dy = g_offset[((b*18 + 2*k    )*Hv + h)*Wv + w];
            float dx = g_offset[((b*18 + 2*k + 1)*Hv + h)*Wv + w];
            float m  = g_mask  [((b*9  + k      )*Hv + h)*Wv + w];
            float py = (float)(h + ky - 1) + dy;
            float px = (float)(w + kx - 1) + dx;
            float y0f = floorf(py), x0f = floorf(px);
            float wy1 = py - y0f, wx1 = px - x0f;
            float wy0 = 1.f - wy1, wx0 = 1.f - wx1;
            int iy0 = (int)y0f, ix0 = (int)x0f;
            bool vy0 = (iy0 >= 0)  && (iy0 < Hv);
            bool vy1 = (iy0 >= -1) && (iy0 < Hv-1);
            bool vx0 = (ix0 >= 0)  && (ix0 < Wv);
            bool vx1 = (ix0 >= -1) && (ix0 < Wv-1);
            sAy[tid] = iy0; sAx[tid] = ix0;
            sAw[tid] = make_float4((vy0 && vx0) ? m*wy0*wx0 : 0.f,
                                   (vy0 && vx1) ? m*wy0*wx1 : 0.f,
                                   (vy1 && vx0) ? m*wy1*wx0 : 0.f,
                                   (vy1 && vx1) ? m*wy1*wx1 : 0.f);
        }
        __syncthreads();

        const float4* xb4 = (const float4*)g_xt + (size_t)b*HWv*16;
        #pragma unroll
        for (int itb = 0; itb < 5; itb++) {
            int it = itb*512 + tid;
            if (it < 2304) {
                int pk = it >> 4, cq = it & 15;
                int iy0 = sAy[pk], ix0 = sAx[pk];
                float4 wg = sAw[pk];
                int y0c = min(Hv-1, max(0, iy0));
                int y1c = min(Hv-1, max(0, iy0 + 1));
                int x0c = min(Wv-1, max(0, ix0));
                int x1c = min(Wv-1, max(0, ix0 + 1));
                float4 v00 = xb4[(y0c*Wv + x0c)*16 + cq];
                float4 v01 = xb4[(y0c*Wv + x1c)*16 + cq];
                float4 v10 = xb4[(y1c*Wv + x0c)*16 + cq];
                float4 v11 = xb4[(y1c*Wv + x1c)*16 + cq];
                float4 r;
                r.x = fmaf(wg.w, v11.x, fmaf(wg.z, v10.x, fmaf(wg.y, v01.x, wg.x*v00.x)));
                r.y = fmaf(wg.w, v11.y, fmaf(wg.z, v10.y, fmaf(wg.y, v01.y, wg.x*v00.y)));
                r.z = fmaf(wg.w, v11.z, fmaf(wg.z, v10.z, fmaf(wg.y, v01.z, wg.x*v00.z)));
                r.w = fmaf(wg.w, v11.w, fmaf(wg.z, v10.w, fmaf(wg.y, v01.w, wg.x*v00.w)));
                int p = pk / 9, k = pk - p*9;
                ((float4*)(ss + p*SS_STRIDE))[k*16 + cq] = r;
            }
        }
        __syncthreads();

        float a00=0,a01=0,a02=0,a03=0, a10=0,a11=0,a12=0,a13=0;
        float a20=0,a21=0,a22=0,a23=0, a30=0,a31=0,a32=0,a33=0;
        #pragma unroll
        for (int q = 0; q < 18; q++) {
            float4 qa = w0p[q], qb = w1p[q], qc = w2p[q], qd = w3p[q];
            float4 s0 = p0p[q], s1 = p1p[q], s2 = p2p[q], s3 = p3p[q];
            a00=fmaf(qa.x,s0.x,a00); a00=fmaf(qa.y,s0.y,a00); a00=fmaf(qa.z,s0.z,a00); a00=fmaf(qa.w,s0.w,a00);
            a01=fmaf(qa.x,s1.x,a01); a01=fmaf(qa.y,s1.y,a01); a01=fmaf(qa.z,s1.z,a01); a01=fmaf(qa.w,s1.w,a01);
            a02=fmaf(qa.x,s2.x,a02); a02=fmaf(qa.y,s2.y,a02); a02=fmaf(qa.z,s2.z,a02); a02=fmaf(qa.w,s2.w,a02);
            a03=fmaf(qa.x,s3.x,a03); a03=fmaf(qa.y,s3.y,a03); a03=fmaf(qa.z,s3.z,a03); a03=fmaf(qa.w,s3.w,a03);
            a10=fmaf(qb.x,s0.x,a10); a10=fmaf(qb.y,s0.y,a10); a10=fmaf(qb.z,s0.z,a10); a10=fmaf(qb.w,s0.w,a10);
            a11=fmaf(qb.x,s1.x,a11); a11=fmaf(qb.y,s1.y,a11); a11=fmaf(qb.z,s1.z,a11); a11=fmaf(qb.w,s1.w,a11);
            a12=fmaf(qb.x,s2.x,a12); a12=fmaf(qb.y,s2.y,a12); a12=fmaf(qb.z,s2.z,a12); a12=fmaf(qb.w,s2.w,a12);
            a13=fmaf(qb.x,s3.x,a13); a13=fmaf(qb.y,s3.y,a13); a13=fmaf(qb.z,s3.z,a13); a13=fmaf(qb.w,s3.w,a13);
            a20=fmaf(qc.x,s0.x,a20); a20=fmaf(qc.y,s0.y,a20); a20=fmaf(qc.z,s0.z,a20); a20=fmaf(qc.w,s0.w,a20);
            a21=fmaf(qc.x,s1.x,a21); a21=fmaf(qc.y,s1.y,a21); a21=fmaf(qc.z,s1.z,a21); a21=fmaf(qc.w,s1.w,a21);
            a22=fmaf(qc.x,s2.x,a22); a22=fmaf(qc.y,s2.y,a22); a22=fmaf(qc.z,s2.z,a22); a22=fmaf(qc.w,s2.w,a22);
            a23=fmaf(qc.x,s3.x,a23); a23=fmaf(qc.y,s3.y,a23); a23=fmaf(qc.z,s3.z,a23); a23=fmaf(qc.w,s3.w,a23);
            a30=fmaf(qd.x,s0.x,a30); a30=fmaf(qd.y,s0.y,a30); a30=fmaf(qd.z,s0.z,a30); a30=fmaf(qd.w,s0.w,a30);
            a31=fmaf(qd.x,s1.x,a31); a31=fmaf(qd.y,s1.y,a31); a31=fmaf(qd.z,s1.z,a31); a31=fmaf(qd.w,s1.w,a31);
            a32=fmaf(qd.x,s2.x,a32); a32=fmaf(qd.y,s2.y,a32); a32=fmaf(qd.z,s2.z,a32); a32=fmaf(qd.w,s2.w,a32);
            a33=fmaf(qd.x,s3.x,a33); a33=fmaf(qd.y,s3.y,a33); a33=fmaf(qd.z,s3.z,a33); a33=fmaf(qd.w,s3.w,a33);
        }
        {
            float4* rp = (float4*)red + ks*272 + og*17 + pg;
            rp[0]  = make_float4(a00,a01,a02,a03);
            rp[4]  = make_float4(a10,a11,a12,a13);
            rp[8]  = make_float4(a20,a21,a22,a23);
            rp[12] = make_float4(a30,a31,a32,a33);
        }
        __syncthreads();

        if (tid < 256) {
            int o = tid >> 2, rpg = tid & 3;
            int base = (o >> 2)*17 + (o & 3)*4 + rpg;
            const float4* r4 = (const float4*)red;
            float4 v0 = r4[base];
            float4 v1 = r4[272  + base];
            float4 v2 = r4[544  + base];
            float4 v3 = r4[816  + base];
            float4 v4 = r4[1088 + base];
            float4 v5 = r4[1360 + base];
            float4 v6 = r4[1632 + base];
            float4 v7 = r4[1904 + base];
            float4 res;
            res.x = ((v0.x+v1.x)+(v2.x+v3.x)) + ((v4.x+v5.x)+(v6.x+v7.x));
            res.y = ((v0.y+v1.y)+(v2.y+v3.y)) + ((v4.y+v5.y)+(v6.y+v7.y));
            res.z = ((v0.z+v1.z)+(v2.z+v3.z)) + ((v4.z+v5.z)+(v6.z+v7.z));
            res.w = ((v0.w+v1.w)+(v2.w+v3.w)) + ((v4.w+v5.w)+(v6.w+v7.w));
            *(float4*)&out[((size_t)(b*Ov + o)*Hv + h)*Wv + w0 + rpg*4] = res;
        }
    }
}

// ---------------------------------------------------------------------------
// BN
// ---------------------------------------------------------------------------
__global__ void reduce_kernel(const float* __restrict__ y) {
    int c = blockIdx.x, b = blockIdx.y, tid = threadIdx.x;
    const float4* p = (const float4*)y + (size_t)(b*Ov + c)*4096;
    float s = 0.f, q = 0.f;
    for (int i = tid; i < 4096; i += 256) {
        float4 v = p[i];
        s += v.x + v.y + v.z + v.w;
        q = fmaf(v.x,v.x,q); q = fmaf(v.y,v.y,q); q = fmaf(v.z,v.z,q); q = fmaf(v.w,v.w,q);
    }
    __shared__ float ssum[8], ssq[8];
    #pragma unroll
    for (int o = 16; o > 0; o >>= 1) {
        s += __shfl_down_sync(0xffffffff, s, o);
        q += __shfl_down_sync(0xffffffff, q, o);
    }
    if ((tid & 31) == 0) { ssum[tid >> 5] = s; ssq[tid >> 5] = q; }
    __syncthreads();
    if (tid < 8) {
        s = ssum[tid]; q = ssq[tid];
        #pragma unroll
        for (int o = 4; o > 0; o >>= 1) {
            s += __shfl_down_sync(0xff, s, o);
            q += __shfl_down_sync(0xff, q, o);
        }
        if (tid == 0) { g_psum[c*Bv + b] = s; g_psq[c*Bv + b] = q; }
    }
}

__global__ void stats_kernel() {
    int c = threadIdx.x;
    float s = 0.f, q = 0.f;
    for (int b = 0; b < Bv; b++) { s += g_psum[c*Bv + b]; q += g_psq[c*Bv + b]; }
    const float inv = 1.f / (float)(Bv*HWv);
    float mean = s * inv;
    float var  = q * inv - mean*mean;
    g_mean[c] = mean;
    g_rstd[c] = rsqrtf(var + 1e-5f);
}

__global__ void bn_kernel(float* __restrict__ y,
                          const float* __restrict__ gamma,
                          const float* __restrict__ beta) {
    int idx = blockIdx.x*256 + threadIdx.x;
    if (idx >= Bv*Ov*HWv/4) return;
    int c = (idx >> 12) & 63;
    float a  = g_rstd[c] * gamma[c];
    float bb = fmaf(-g_mean[c], a, beta[c]);
    float4* p = (float4*)y;
    float4 v = p[idx];
    v.x = fmaxf(fmaf(v.x, a, bb), 0.f);
    v.y = fmaxf(fmaf(v.y, a, bb), 0.f);
    v.z = fmaxf(fmaf(v.z, a, bb), 0.f);
    v.w = fmaxf(fmaf(v.w, a, bb), 0.f);
    p[idx] = v;
}

// ---------------------------------------------------------------------------
extern "C" void kernel_launch(void* const* d_in, const int* in_sizes, int n_in,
                              void* d_out, int out_size) {
    const float* x     = (const float*)d_in[0];
    const float* wh    = (const float*)d_in[1];
    const float* bh    = (const float*)d_in[2];
    const float* wv    = (const float*)d_in[3];
    const float* bv    = (const float*)d_in[4];
    const float* wm    = (const float*)d_in[5];
    const float* bm    = (const float*)d_in[6];
    const float* wd    = (const float*)d_in[7];
    const float* gamma = (const float*)d_in[8];
    const float* beta  = (const float*)d_in[9];
    float* out = (float*)d_out;

    const int deform_smem = SMEM_FLOATS * 4;   // 231040 B
    cudaFuncSetAttribute(deform_kernel, cudaFuncAttributeMaxDynamicSharedMemorySize, deform_smem);

    pack_kernel<<<(18432 + 6912 + 36864 + 255)/256, 256>>>(wh, wv, wm, wd);
    transpose_kernel<<<dim3(HWv/32, Cv/32, Bv), dim3(32, 8)>>>(x);
    offmask_kernel<<<dim3(Wv/32, Hv/8, Bv), 128>>>(x, bh, bv, bm);
    deform_kernel<<<1024, 512, deform_smem>>>(out);
    reduce_kernel<<<dim3(Ov, Bv), 256>>>(out);
    stats_kernel<<<1, Ov>>>();
    bn_kernel<<<(Bv*Ov*HWv/4 + 255)/256, 256>>>(out, gamma, beta);
}

// round 9
// speedup vs baseline: 1.5115x; 1.0074x over previous
#include <cuda_runtime.h>
#include <math.h>

#define Bv 8
#define Cv 64
#define Hv 128
#define Wv 128
#define Ov 64
#define HWv (Hv*Wv)

// scratch (__device__ globals; no allocation allowed)
__device__ float g_offset[Bv*18*HWv];   // (B,18,H,W)
__device__ float g_mask[Bv*9*HWv];      // (B,9,H,W)
__device__ float g_xt[(size_t)Bv*HWv*Cv]; // (B,H,W,C)
__device__ float g_whP[Cv*18*16];
__device__ float g_wvP[Cv*18*16];
__device__ float g_wmP[Cv*9*12];
__device__ float g_wdT[Ov*576];         // [o][j], j = k*16 + c/4 (float4 granules)
__device__ float g_psum[Ov];
__device__ float g_psq[Ov];
__device__ float g_mean[Ov];
__device__ float g_rstd[Ov];

// ---------------------------------------------------------------------------
// weight packer (+ zero the fused BN accumulators each launch)
// ---------------------------------------------------------------------------
__global__ void pack_kernel(const float* __restrict__ wh, const float* __restrict__ wv,
                            const float* __restrict__ wm, const float* __restrict__ wd) {
    int idx = blockIdx.x*256 + threadIdx.x;
    if (blockIdx.x == 0 && threadIdx.x < Ov) {
        g_psum[threadIdx.x] = 0.f;
        g_psq[threadIdx.x]  = 0.f;
    }
    if (idx < 18432) {
        int c = idx/288, r = idx - c*288, o = r >> 4, k = r & 15;
        g_whP[idx] = (k < 15) ? wh[(o*Cv + c)*15 + k] : 0.f;
        g_wvP[idx] = (k < 15) ? wv[(o*Cv + c)*15 + k] : 0.f;
    } else if (idx < 18432 + 6912) {
        int j = idx - 18432;
        int c = j/108, r = j - c*108, o = r/12, k = r - o*12;
        g_wmP[j] = (k < 9) ? wm[(o*Cv + c)*9 + k] : 0.f;
    } else if (idx < 18432 + 6912 + 36864) {
        int j = idx - 18432 - 6912;
        int o = j/576, r = j - o*576, k = r >> 6, c = r & 63;
        g_wdT[j] = wd[(o*Cv + c)*9 + k];
    }
}

// ---------------------------------------------------------------------------
// x (B,C,HW) -> xt (B,HW,C)
// ---------------------------------------------------------------------------
__global__ void transpose_kernel(const float* __restrict__ x) {
    __shared__ float t[32][33];
    int b = blockIdx.z;
    int hw0 = blockIdx.x * 32;
    int c0  = blockIdx.y * 32;
    int tx = threadIdx.x, ty = threadIdx.y;
    #pragma unroll
    for (int j = 0; j < 4; j++) {
        int c = c0 + ty + j*8;
        t[ty + j*8][tx] = x[((size_t)b*Cv + c)*HWv + hw0 + tx];
    }
    __syncthreads();
    #pragma unroll
    for (int j = 0; j < 4; j++) {
        int hw = hw0 + ty + j*8;
        g_xt[((size_t)b*HWv + hw)*Cv + c0 + tx] = t[tx][ty + j*8];
    }
}

// ---------------------------------------------------------------------------
// fused offset(18ch) + mask(9ch), 32x8 tile, 128 threads, 2 px/thread
// occupancy 4 -> single wave (measured win in R7)
// ---------------------------------------------------------------------------
__global__ void __launch_bounds__(128, 4) offmask_kernel(
    const float* __restrict__ x,
    const float* __restrict__ bh, const float* __restrict__ bv,
    const float* __restrict__ bm)
{
    __shared__ float tiles[2][22*47];
    int b  = blockIdx.z;
    int h0 = blockIdx.y * 8;
    int wb = blockIdx.x * 32;
    int tid = threadIdx.x;
    int tx = tid & 15, ty = tid >> 4;
    int h = h0 + ty;
    int w = wb + 2*tx;

    int  soff[8], sidx[8];
    #pragma unroll
    for (int s = 0; s < 8; s++) {
        int i = tid + s*128;
        if (i < 22*46) {
            int r = i / 46, cc = i - r*46;
            int gh = h0 + r - 7, gw = wb + cc - 7;
            sidx[s] = r*47 + cc;
            soff[s] = (gh >= 0 && gh < Hv && gw >= 0 && gw < Wv) ? gh*Wv + gw : -1;
        } else { sidx[s] = -1; soff[s] = -1; }
    }

    float acc0[18], acc1[18], am0[9], am1[9];
    #pragma unroll
    for (int o = 0; o < 18; o++) { float bo = bh[o] + bv[o]; acc0[o] = bo; acc1[o] = bo; }
    #pragma unroll
    for (int o = 0; o < 9; o++)  { float bo = bm[o]; am0[o] = bo; am1[o] = bo; }

    const float* xb = x + (size_t)b*Cv*HWv;

    {
        const float* xc = xb;
        #pragma unroll
        for (int s = 0; s < 8; s++)
            if (sidx[s] >= 0) tiles[0][sidx[s]] = (soff[s] >= 0) ? __ldg(xc + soff[s]) : 0.f;
    }

    for (int c = 0; c < Cv; c++) {
        __syncthreads();
        if (c + 1 < Cv) {
            const float* xc = xb + (c+1)*HWv;
            float* dst = tiles[(c+1) & 1];
            #pragma unroll
            for (int s = 0; s < 8; s++)
                if (sidx[s] >= 0) dst[sidx[s]] = (soff[s] >= 0) ? __ldg(xc + soff[s]) : 0.f;
        }
        const float* tile = tiles[c & 1];

        float xr[16];
        #pragma unroll
        for (int i = 0; i < 16; i++) xr[i] = tile[(ty+7)*47 + 2*tx + i];
        float xcA[15], xcB[15];
        #pragma unroll
        for (int i = 0; i < 15; i++) {
            xcA[i] = tile[(ty+i)*47 + 2*tx + 7];
            xcB[i] = tile[(ty+i)*47 + 2*tx + 8];
        }
        float t00 = tile[(ty+6)*47 + 2*tx + 6];
        float t01 = tile[(ty+6)*47 + 2*tx + 9];
        float t10 = tile[(ty+8)*47 + 2*tx + 6];
        float t11 = tile[(ty+8)*47 + 2*tx + 9];

        const float4* whc = (const float4*)(g_whP + c*288);
        const float4* wvc = (const float4*)(g_wvP + c*288);
        const float4* wmc = (const float4*)(g_wmP + c*108);
        #pragma unroll
        for (int o = 0; o < 18; o++) {
            float4 q0 = whc[o*4+0], q1 = whc[o*4+1], q2 = whc[o*4+2], q3 = whc[o*4+3];
            float wkh[15] = {q0.x,q0.y,q0.z,q0.w, q1.x,q1.y,q1.z,q1.w,
                             q2.x,q2.y,q2.z,q2.w, q3.x,q3.y,q3.z};
            float a0 = acc0[o], a1 = acc1[o];
            #pragma unroll
            for (int k = 0; k < 15; k++) {
                a0 = fmaf(xr[k],   wkh[k], a0);
                a1 = fmaf(xr[k+1], wkh[k], a1);
            }
            float4 v0 = wvc[o*4+0], v1 = wvc[o*4+1], v2 = wvc[o*4+2], v3 = wvc[o*4+3];
            float wkv[15] = {v0.x,v0.y,v0.z,v0.w, v1.x,v1.y,v1.z,v1.w,
                             v2.x,v2.y,v2.z,v2.w, v3.x,v3.y,v3.z};
            #pragma unroll
            for (int k = 0; k < 15; k++) {
                a0 = fmaf(xcA[k], wkv[k], a0);
                a1 = fmaf(xcB[k], wkv[k], a1);
            }
            acc0[o] = a0; acc1[o] = a1;
        }
        #pragma unroll
        for (int o = 0; o < 9; o++) {
            float4 q0 = wmc[o*3], q1 = wmc[o*3+1], q2 = wmc[o*3+2];
            float m0 = am0[o], m1 = am1[o];
            m0 = fmaf(t00,    q0.x, m0);  m1 = fmaf(xcA[6], q0.x, m1);
            m0 = fmaf(xcA[6], q0.y, m0);  m1 = fmaf(xcB[6], q0.y, m1);
            m0 = fmaf(xcB[6], q0.z, m0);  m1 = fmaf(t01,    q0.z, m1);
            m0 = fmaf(xr[6],  q0.w, m0);  m1 = fmaf(xr[7],  q0.w, m1);
            m0 = fmaf(xr[7],  q1.x, m0);  m1 = fmaf(xr[8],  q1.x, m1);
            m0 = fmaf(xr[8],  q1.y, m0);  m1 = fmaf(xr[9],  q1.y, m1);
            m0 = fmaf(t10,    q1.z, m0);  m1 = fmaf(xcA[8], q1.z, m1);
            m0 = fmaf(xcA[8], q1.w, m0);  m1 = fmaf(xcB[8], q1.w, m1);
            m0 = fmaf(xcB[8], q2.x, m0);  m1 = fmaf(t11,    q2.x, m1);
            am0[o] = m0; am1[o] = m1;
        }
    }

    #pragma unroll
    for (int o = 0; o < 18; o++) {
        float2 v; v.x = acc0[o]; v.y = acc1[o];
        *(float2*)&g_offset[((b*18 + o)*Hv + h)*Wv + w] = v;
    }
    #pragma unroll
    for (int o = 0; o < 9; o++) {
        float2 v;
        v.x = 1.f/(1.f + __expf(-am0[o]));
        v.y = 1.f/(1.f + __expf(-am1[o]));
        *(float2*)&g_mask[((b*9 + o)*Hv + h)*Wv + w] = v;
    }
}

// ---------------------------------------------------------------------------
// deform (R6/R8 config) + fused BN-stat accumulation in the epilogue
// ---------------------------------------------------------------------------
#define SW_STRIDE 608
#define SW_FLOATS 38912
#define SS_STRIDE 580
#define RED_SLICE 1088
#define OFF_SS   SW_FLOATS
#define OFF_RED  (OFF_SS + 16*SS_STRIDE)
#define OFF_SAY  (OFF_RED + 8*RED_SLICE)
#define OFF_SAX  (OFF_SAY + 144)
#define OFF_SAW  (OFF_SAX + 144)
#define SMEM_FLOATS (OFF_SAW + 576)     // 57760 floats = 231040 B

__device__ __forceinline__ int wrow_off(int o) {
    return o*SW_STRIDE + ((o >> 2) & 7)*4;
}

__global__ void __launch_bounds__(512, 1) deform_kernel(float* __restrict__ out) {
    extern __shared__ float smem[];
    float* sw  = smem;
    float* ss  = smem + OFF_SS;
    float* red = smem + OFF_RED;
    int*  sAy  = (int*)(smem + OFF_SAY);
    int*  sAx  = (int*)(smem + OFF_SAX);
    float4* sAw = (float4*)(smem + OFF_SAW);
    int tid = threadIdx.x;

    const float4* wt4 = (const float4*)g_wdT;
    for (int i = tid; i < 64*144; i += 512) {
        int o = i / 144, q = i - o*144;
        ((float4*)(sw + wrow_off(o)))[q] = wt4[i];
    }

    int h  = blockIdx.x >> 3;
    int w0 = (blockIdx.x & 7) << 4;

    int og = tid & 15;
    int pg = (tid >> 4) & 3;
    int ks = tid >> 6;
    const float4* w0p = (const float4*)(sw + wrow_off(og*4+0)) + ks*18;
    const float4* w1p = (const float4*)(sw + wrow_off(og*4+1)) + ks*18;
    const float4* w2p = (const float4*)(sw + wrow_off(og*4+2)) + ks*18;
    const float4* w3p = (const float4*)(sw + wrow_off(og*4+3)) + ks*18;
    const float4* p0p = (const float4*)(ss + (pg*4+0)*SS_STRIDE) + ks*18;
    const float4* p1p = (const float4*)(ss + (pg*4+1)*SS_STRIDE) + ks*18;
    const float4* p2p = (const float4*)(ss + (pg*4+2)*SS_STRIDE) + ks*18;
    const float4* p3p = (const float4*)(ss + (pg*4+3)*SS_STRIDE) + ks*18;

    float bn_s = 0.f, bn_q = 0.f;   // fused BN partials (valid for tid<256)

    for (int b = 0; b < Bv; b++) {
        __syncthreads();
        if (tid < 144) {
            int p = tid / 9, k = tid - p*9;
            int w = w0 + p;
            int ky = k / 3, kx = k - ky*3;
            float dy = g_offset[((b*18 + 2*k    )*Hv + h)*Wv + w];
            float dx = g_offset[((b*18 + 2*k + 1)*Hv + h)*Wv + w];
            float m  = g_mask  [((b*9  + k      )*Hv + h)*Wv + w];
            float py = (float)(h + ky - 1) + dy;
            float px = (float)(w + kx - 1) + dx;
            float y0f = floorf(py), x0f = floorf(px);
            float wy1 = py - y0f, wx1 = px - x0f;
            float wy0 = 1.f - wy1, wx0 = 1.f - wx1;
            int iy0 = (int)y0f, ix0 = (int)x0f;
            bool vy0 = (iy0 >= 0)  && (iy0 < Hv);
            bool vy1 = (iy0 >= -1) && (iy0 < Hv-1);
            bool vx0 = (ix0 >= 0)  && (ix0 < Wv);
            bool vx1 = (ix0 >= -1) && (ix0 < Wv-1);
            sAy[tid] = iy0; sAx[tid] = ix0;
            sAw[tid] = make_float4((vy0 && vx0) ? m*wy0*wx0 : 0.f,
                                   (vy0 && vx1) ? m*wy0*wx1 : 0.f,
                                   (vy1 && vx0) ? m*wy1*wx0 : 0.f,
                                   (vy1 && vx1) ? m*wy1*wx1 : 0.f);
        }
        __syncthreads();

        const float4* xb4 = (const float4*)g_xt + (size_t)b*HWv*16;
        #pragma unroll
        for (int itb = 0; itb < 5; itb++) {
            int it = itb*512 + tid;
            if (it < 2304) {
                int pk = it >> 4, cq = it & 15;
                int iy0 = sAy[pk], ix0 = sAx[pk];
                float4 wg = sAw[pk];
                int y0c = min(Hv-1, max(0, iy0));
                int y1c = min(Hv-1, max(0, iy0 + 1));
                int x0c = min(Wv-1, max(0, ix0));
                int x1c = min(Wv-1, max(0, ix0 + 1));
                float4 v00 = xb4[(y0c*Wv + x0c)*16 + cq];
                float4 v01 = xb4[(y0c*Wv + x1c)*16 + cq];
                float4 v10 = xb4[(y1c*Wv + x0c)*16 + cq];
                float4 v11 = xb4[(y1c*Wv + x1c)*16 + cq];
                float4 r;
                r.x = fmaf(wg.w, v11.x, fmaf(wg.z, v10.x, fmaf(wg.y, v01.x, wg.x*v00.x)));
                r.y = fmaf(wg.w, v11.y, fmaf(wg.z, v10.y, fmaf(wg.y, v01.y, wg.x*v00.y)));
                r.z = fmaf(wg.w, v11.z, fmaf(wg.z, v10.z, fmaf(wg.y, v01.z, wg.x*v00.z)));
                r.w = fmaf(wg.w, v11.w, fmaf(wg.z, v10.w, fmaf(wg.y, v01.w, wg.x*v00.w)));
                int p = pk / 9, k = pk - p*9;
                ((float4*)(ss + p*SS_STRIDE))[k*16 + cq] = r;
            }
        }
        __syncthreads();

        float a00=0,a01=0,a02=0,a03=0, a10=0,a11=0,a12=0,a13=0;
        float a20=0,a21=0,a22=0,a23=0, a30=0,a31=0,a32=0,a33=0;
        #pragma unroll
        for (int q = 0; q < 18; q++) {
            float4 qa = w0p[q], qb = w1p[q], qc = w2p[q], qd = w3p[q];
            float4 s0 = p0p[q], s1 = p1p[q], s2 = p2p[q], s3 = p3p[q];
            a00=fmaf(qa.x,s0.x,a00); a00=fmaf(qa.y,s0.y,a00); a00=fmaf(qa.z,s0.z,a00); a00=fmaf(qa.w,s0.w,a00);
            a01=fmaf(qa.x,s1.x,a01); a01=fmaf(qa.y,s1.y,a01); a01=fmaf(qa.z,s1.z,a01); a01=fmaf(qa.w,s1.w,a01);
            a02=fmaf(qa.x,s2.x,a02); a02=fmaf(qa.y,s2.y,a02); a02=fmaf(qa.z,s2.z,a02); a02=fmaf(qa.w,s2.w,a02);
            a03=fmaf(qa.x,s3.x,a03); a03=fmaf(qa.y,s3.y,a03); a03=fmaf(qa.z,s3.z,a03); a03=fmaf(qa.w,s3.w,a03);
            a10=fmaf(qb.x,s0.x,a10); a10=fmaf(qb.y,s0.y,a10); a10=fmaf(qb.z,s0.z,a10); a10=fmaf(qb.w,s0.w,a10);
            a11=fmaf(qb.x,s1.x,a11); a11=fmaf(qb.y,s1.y,a11); a11=fmaf(qb.z,s1.z,a11); a11=fmaf(qb.w,s1.w,a11);
            a12=fmaf(qb.x,s2.x,a12); a12=fmaf(qb.y,s2.y,a12); a12=fmaf(qb.z,s2.z,a12); a12=fmaf(qb.w,s2.w,a12);
            a13=fmaf(qb.x,s3.x,a13); a13=fmaf(qb.y,s3.y,a13); a13=fmaf(qb.z,s3.z,a13); a13=fmaf(qb.w,s3.w,a13);
            a20=fmaf(qc.x,s0.x,a20); a20=fmaf(qc.y,s0.y,a20); a20=fmaf(qc.z,s0.z,a20); a20=fmaf(qc.w,s0.w,a20);
            a21=fmaf(qc.x,s1.x,a21); a21=fmaf(qc.y,s1.y,a21); a21=fmaf(qc.z,s1.z,a21); a21=fmaf(qc.w,s1.w,a21);
            a22=fmaf(qc.x,s2.x,a22); a22=fmaf(qc.y,s2.y,a22); a22=fmaf(qc.z,s2.z,a22); a22=fmaf(qc.w,s2.w,a22);
            a23=fmaf(qc.x,s3.x,a23); a23=fmaf(qc.y,s3.y,a23); a23=fmaf(qc.z,s3.z,a23); a23=fmaf(qc.w,s3.w,a23);
            a30=fmaf(qd.x,s0.x,a30); a30=fmaf(qd.y,s0.y,a30); a30=fmaf(qd.z,s0.z,a30); a30=fmaf(qd.w,s0.w,a30);
            a31=fmaf(qd.x,s1.x,a31); a31=fmaf(qd.y,s1.y,a31); a31=fmaf(qd.z,s1.z,a31); a31=fmaf(qd.w,s1.w,a31);
            a32=fmaf(qd.x,s2.x,a32); a32=fmaf(qd.y,s2.y,a32); a32=fmaf(qd.z,s2.z,a32); a32=fmaf(qd.w,s2.w,a32);
            a33=fmaf(qd.x,s3.x,a33); a33=fmaf(qd.y,s3.y,a33); a33=fmaf(qd.z,s3.z,a33); a33=fmaf(qd.w,s3.w,a33);
        }
        {
            float4* rp = (float4*)red + ks*272 + og*17 + pg;
            rp[0]  = make_float4(a00,a01,a02,a03);
            rp[4]  = make_float4(a10,a11,a12,a13);
            rp[8]  = make_float4(a20,a21,a22,a23);
            rp[12] = make_float4(a30,a31,a32,a33);
        }
        __syncthreads();

        if (tid < 256) {
            int o = tid >> 2, rpg = tid & 3;
            int base = (o >> 2)*17 + (o & 3)*4 + rpg;
            const float4* r4 = (const float4*)red;
            float4 v0 = r4[base];
            float4 v1 = r4[272  + base];
            float4 v2 = r4[544  + base];
            float4 v3 = r4[816  + base];
            float4 v4 = r4[1088 + base];
            float4 v5 = r4[1360 + base];
            float4 v6 = r4[1632 + base];
            float4 v7 = r4[1904 + base];
            float4 res;
            res.x = ((v0.x+v1.x)+(v2.x+v3.x)) + ((v4.x+v5.x)+(v6.x+v7.x));
            res.y = ((v0.y+v1.y)+(v2.y+v3.y)) + ((v4.y+v5.y)+(v6.y+v7.y));
            res.z = ((v0.z+v1.z)+(v2.z+v3.z)) + ((v4.z+v5.z)+(v6.z+v7.z));
            res.w = ((v0.w+v1.w)+(v2.w+v3.w)) + ((v4.w+v5.w)+(v6.w+v7.w));
            *(float4*)&out[((size_t)(b*Ov + o)*Hv + h)*Wv + w0 + rpg*4] = res;
            // fused BN partials
            bn_s += (res.x + res.y) + (res.z + res.w);
            bn_q += fmaf(res.x,res.x, fmaf(res.y,res.y, fmaf(res.z,res.z, res.w*res.w)));
        }
    }

    // reduce BN partials over the 4 pixel-group lanes sharing an o, then atomic
    if (tid < 256) {
        bn_s += __shfl_xor_sync(0xffffffff, bn_s, 1);
        bn_q += __shfl_xor_sync(0xffffffff, bn_q, 1);
        bn_s += __shfl_xor_sync(0xffffffff, bn_s, 2);
        bn_q += __shfl_xor_sync(0xffffffff, bn_q, 2);
        if ((tid & 3) == 0) {
            int o = tid >> 2;
            atomicAdd(&g_psum[o], bn_s);
            atomicAdd(&g_psq[o],  bn_q);
        }
    }
}

// ---------------------------------------------------------------------------
// BN stats (tiny) + normalize
// ---------------------------------------------------------------------------
__global__ void stats_kernel() {
    int c = threadIdx.x;
    const float inv = 1.f / (float)(Bv*HWv);
    float mean = g_psum[c] * inv;
    float var  = g_psq[c] * inv - mean*mean;
    g_mean[c] = mean;
    g_rstd[c] = rsqrtf(var + 1e-5f);
}

__global__ void bn_kernel(float* __restrict__ y,
                          const float* __restrict__ gamma,
                          const float* __restrict__ beta) {
    int idx = blockIdx.x*256 + threadIdx.x;
    if (idx >= Bv*Ov*HWv/4) return;
    int c = (idx >> 12) & 63;
    float a  = g_rstd[c] * gamma[c];
    float bb = fmaf(-g_mean[c], a, beta[c]);
    float4* p = (float4*)y;
    float4 v = p[idx];
    v.x = fmaxf(fmaf(v.x, a, bb), 0.f);
    v.y = fmaxf(fmaf(v.y, a, bb), 0.f);
    v.z = fmaxf(fmaf(v.z, a, bb), 0.f);
    v.w = fmaxf(fmaf(v.w, a, bb), 0.f);
    p[idx] = v;
}

// ---------------------------------------------------------------------------
extern "C" void kernel_launch(void* const* d_in, const int* in_sizes, int n_in,
                              void* d_out, int out_size) {
    const float* x     = (const float*)d_in[0];
    const float* wh    = (const float*)d_in[1];
    const float* bh    = (const float*)d_in[2];
    const float* wv    = (const float*)d_in[3];
    const float* bv    = (const float*)d_in[4];
    const float* wm    = (const float*)d_in[5];
    const float* bm    = (const float*)d_in[6];
    const float* wd    = (const float*)d_in[7];
    const float* gamma = (const float*)d_in[8];
    const float* beta  = (const float*)d_in[9];
    float* out = (float*)d_out;

    const int deform_smem = SMEM_FLOATS * 4;   // 231040 B
    cudaFuncSetAttribute(deform_kernel, cudaFuncAttributeMaxDynamicSharedMemorySize, deform_smem);

    pack_kernel<<<(18432 + 6912 + 36864 + 255)/256, 256>>>(wh, wv, wm, wd);
    transpose_kernel<<<dim3(HWv/32, Cv/32, Bv), dim3(32, 8)>>>(x);
    offmask_kernel<<<dim3(Wv/32, Hv/8, Bv), 128>>>(x, bh, bv, bm);
    deform_kernel<<<1024, 512, deform_smem>>>(out);
    stats_kernel<<<1, Ov>>>();
    bn_kernel<<<(Bv*Ov*HWv/4 + 255)/256, 256>>>(out, gamma, beta);
}

// round 11
// speedup vs baseline: 1.5535x; 1.0278x over previous
#include <cuda_runtime.h>
#include <math.h>

#define Bv 8
#define Cv 64
#define Hv 128
#define Wv 128
#define Ov 64
#define HWv (Hv*Wv)

// scratch (__device__ globals; no allocation allowed)
__device__ float g_offset[Bv*18*HWv];   // (B,18,H,W)
__device__ float g_mask[Bv*9*HWv];      // (B,9,H,W)
__device__ float g_xt[(size_t)Bv*HWv*Cv]; // (B,H,W,C)
__device__ float g_whP[Cv*18*16];
__device__ float g_wvP[Cv*18*16];
__device__ float g_wmP[Cv*9*12];
__device__ float g_wdT[Ov*576];         // [o][j], j = k*16 + c/4 (float4 granules)
__device__ float g_psum[Ov];
__device__ float g_psq[Ov];
__device__ float g_mean[Ov];
__device__ float g_rstd[Ov];

// ---------------------------------------------------------------------------
// weight packer (+ zero the fused BN accumulators each launch)
// ---------------------------------------------------------------------------
__global__ void pack_kernel(const float* __restrict__ wh, const float* __restrict__ wv,
                            const float* __restrict__ wm, const float* __restrict__ wd) {
    int idx = blockIdx.x*256 + threadIdx.x;
    if (blockIdx.x == 0 && threadIdx.x < Ov) {
        g_psum[threadIdx.x] = 0.f;
        g_psq[threadIdx.x]  = 0.f;
    }
    if (idx < 18432) {
        int c = idx/288, r = idx - c*288, o = r >> 4, k = r & 15;
        g_whP[idx] = (k < 15) ? wh[(o*Cv + c)*15 + k] : 0.f;
        g_wvP[idx] = (k < 15) ? wv[(o*Cv + c)*15 + k] : 0.f;
    } else if (idx < 18432 + 6912) {
        int j = idx - 18432;
        int c = j/108, r = j - c*108, o = r/12, k = r - o*12;
        g_wmP[j] = (k < 9) ? wm[(o*Cv + c)*9 + k] : 0.f;
    } else if (idx < 18432 + 6912 + 36864) {
        int j = idx - 18432 - 6912;
        int o = j/576, r = j - o*576, k = r >> 6, c = r & 63;
        g_wdT[j] = wd[(o*Cv + c)*9 + k];
    }
}

// ---------------------------------------------------------------------------
// x (B,C,HW) -> xt (B,HW,C)
// ---------------------------------------------------------------------------
__global__ void transpose_kernel(const float* __restrict__ x) {
    __shared__ float t[32][33];
    int b = blockIdx.z;
    int hw0 = blockIdx.x * 32;
    int c0  = blockIdx.y * 32;
    int tx = threadIdx.x, ty = threadIdx.y;
    #pragma unroll
    for (int j = 0; j < 4; j++) {
        int c = c0 + ty + j*8;
        t[ty + j*8][tx] = x[((size_t)b*Cv + c)*HWv + hw0 + tx];
    }
    __syncthreads();
    #pragma unroll
    for (int j = 0; j < 4; j++) {
        int hw = hw0 + ty + j*8;
        g_xt[((size_t)b*HWv + hw)*Cv + c0 + tx] = t[tx][ty + j*8];
    }
}

// ---------------------------------------------------------------------------
// fused offset(18ch) + mask(9ch), 32x8 tile, 128 threads, 2 px/thread
// ---------------------------------------------------------------------------
__global__ void __launch_bounds__(128, 4) offmask_kernel(
    const float* __restrict__ x,
    const float* __restrict__ bh, const float* __restrict__ bv,
    const float* __restrict__ bm)
{
    __shared__ float tiles[2][22*47];
    int b  = blockIdx.z;
    int h0 = blockIdx.y * 8;
    int wb = blockIdx.x * 32;
    int tid = threadIdx.x;
    int tx = tid & 15, ty = tid >> 4;
    int h = h0 + ty;
    int w = wb + 2*tx;

    int  soff[8], sidx[8];
    #pragma unroll
    for (int s = 0; s < 8; s++) {
        int i = tid + s*128;
        if (i < 22*46) {
            int r = i / 46, cc = i - r*46;
            int gh = h0 + r - 7, gw = wb + cc - 7;
            sidx[s] = r*47 + cc;
            soff[s] = (gh >= 0 && gh < Hv && gw >= 0 && gw < Wv) ? gh*Wv + gw : -1;
        } else { sidx[s] = -1; soff[s] = -1; }
    }

    float acc0[18], acc1[18], am0[9], am1[9];
    #pragma unroll
    for (int o = 0; o < 18; o++) { float bo = bh[o] + bv[o]; acc0[o] = bo; acc1[o] = bo; }
    #pragma unroll
    for (int o = 0; o < 9; o++)  { float bo = bm[o]; am0[o] = bo; am1[o] = bo; }

    const float* xb = x + (size_t)b*Cv*HWv;

    {
        const float* xc = xb;
        #pragma unroll
        for (int s = 0; s < 8; s++)
            if (sidx[s] >= 0) tiles[0][sidx[s]] = (soff[s] >= 0) ? __ldg(xc + soff[s]) : 0.f;
    }

    for (int c = 0; c < Cv; c++) {
        __syncthreads();
        if (c + 1 < Cv) {
            const float* xc = xb + (c+1)*HWv;
            float* dst = tiles[(c+1) & 1];
            #pragma unroll
            for (int s = 0; s < 8; s++)
                if (sidx[s] >= 0) dst[sidx[s]] = (soff[s] >= 0) ? __ldg(xc + soff[s]) : 0.f;
        }
        const float* tile = tiles[c & 1];

        float xr[16];
        #pragma unroll
        for (int i = 0; i < 16; i++) xr[i] = tile[(ty+7)*47 + 2*tx + i];
        float xcA[15], xcB[15];
        #pragma unroll
        for (int i = 0; i < 15; i++) {
            xcA[i] = tile[(ty+i)*47 + 2*tx + 7];
            xcB[i] = tile[(ty+i)*47 + 2*tx + 8];
        }
        float t00 = tile[(ty+6)*47 + 2*tx + 6];
        float t01 = tile[(ty+6)*47 + 2*tx + 9];
        float t10 = tile[(ty+8)*47 + 2*tx + 6];
        float t11 = tile[(ty+8)*47 + 2*tx + 9];

        const float4* whc = (const float4*)(g_whP + c*288);
        const float4* wvc = (const float4*)(g_wvP + c*288);
        const float4* wmc = (const float4*)(g_wmP + c*108);
        #pragma unroll
        for (int o = 0; o < 18; o++) {
            float4 q0 = whc[o*4+0], q1 = whc[o*4+1], q2 = whc[o*4+2], q3 = whc[o*4+3];
            float wkh[15] = {q0.x,q0.y,q0.z,q0.w, q1.x,q1.y,q1.z,q1.w,
                             q2.x,q2.y,q2.z,q2.w, q3.x,q3.y,q3.z};
            float a0 = acc0[o], a1 = acc1[o];
            #pragma unroll
            for (int k = 0; k < 15; k++) {
                a0 = fmaf(xr[k],   wkh[k], a0);
                a1 = fmaf(xr[k+1], wkh[k], a1);
            }
            float4 v0 = wvc[o*4+0], v1 = wvc[o*4+1], v2 = wvc[o*4+2], v3 = wvc[o*4+3];
            float wkv[15] = {v0.x,v0.y,v0.z,v0.w, v1.x,v1.y,v1.z,v1.w,
                             v2.x,v2.y,v2.z,v2.w, v3.x,v3.y,v3.z};
            #pragma unroll
            for (int k = 0; k < 15; k++) {
                a0 = fmaf(xcA[k], wkv[k], a0);
                a1 = fmaf(xcB[k], wkv[k], a1);
            }
            acc0[o] = a0; acc1[o] = a1;
        }
        #pragma unroll
        for (int o = 0; o < 9; o++) {
            float4 q0 = wmc[o*3], q1 = wmc[o*3+1], q2 = wmc[o*3+2];
            float m0 = am0[o], m1 = am1[o];
            m0 = fmaf(t00,    q0.x, m0);  m1 = fmaf(xcA[6], q0.x, m1);
            m0 = fmaf(xcA[6], q0.y, m0);  m1 = fmaf(xcB[6], q0.y, m1);
            m0 = fmaf(xcB[6], q0.z, m0);  m1 = fmaf(t01,    q0.z, m1);
            m0 = fmaf(xr[6],  q0.w, m0);  m1 = fmaf(xr[7],  q0.w, m1);
            m0 = fmaf(xr[7],  q1.x, m0);  m1 = fmaf(xr[8],  q1.x, m1);
            m0 = fmaf(xr[8],  q1.y, m0);  m1 = fmaf(xr[9],  q1.y, m1);
            m0 = fmaf(t10,    q1.z, m0);  m1 = fmaf(xcA[8], q1.z, m1);
            m0 = fmaf(xcA[8], q1.w, m0);  m1 = fmaf(xcB[8], q1.w, m1);
            m0 = fmaf(xcB[8], q2.x, m0);  m1 = fmaf(t11,    q2.x, m1);
            am0[o] = m0; am1[o] = m1;
        }
    }

    #pragma unroll
    for (int o = 0; o < 18; o++) {
        float2 v; v.x = acc0[o]; v.y = acc1[o];
        *(float2*)&g_offset[((b*18 + o)*Hv + h)*Wv + w] = v;
    }
    #pragma unroll
    for (int o = 0; o < 9; o++) {
        float2 v;
        v.x = 1.f/(1.f + __expf(-am0[o]));
        v.y = 1.f/(1.f + __expf(-am1[o]));
        *(float2*)&g_mask[((b*9 + o)*Hv + h)*Wv + w] = v;
    }
}

// ---------------------------------------------------------------------------
// deform, software-pipelined: gather(b+1) -> registers overlaps GEMM(b)
// RACE FIX vs R10: barrier after the prologue gather — pre-loop GATH(0) reads
// of sAc/sAw must complete before iteration 0's COMPUTE_A(1) overwrites them.
// (Steady-state pairs are separated by barrier Y; the prologue pair was not.)
// ---------------------------------------------------------------------------
#define SW_STRIDE 608
#define SW_FLOATS 38912
#define SS_STRIDE 580
#define OFF_SS   SW_FLOATS                    // 9280 floats
#define OFF_RED  (OFF_SS + 16*SS_STRIDE)      // 8704 floats
#define OFF_SAC  (OFF_RED + 8*1088)           // int4[144] = 576 floats
#define OFF_SAW  (OFF_SAC + 576)              // float4[144] = 576 floats
#define SMEM_FLOATS (OFF_SAW + 576)           // 58048 floats = 232192 B

__device__ __forceinline__ int wrow_off(int o) {
    return o*SW_STRIDE + ((o >> 2) & 7)*4;
}

__global__ void __launch_bounds__(512, 1) deform_kernel(float* __restrict__ out) {
    extern __shared__ float smem[];
    float* sw   = smem;
    float* ss   = smem + OFF_SS;
    float* red  = smem + OFF_RED;
    int4*  sAc  = (int4*)(smem + OFF_SAC);
    float4* sAwf = (float4*)(smem + OFF_SAW);
    int tid = threadIdx.x;

    const float4* wt4 = (const float4*)g_wdT;
    for (int i = tid; i < 64*144; i += 512) {
        int o = i / 144, q = i - o*144;
        ((float4*)(sw + wrow_off(o)))[q] = wt4[i];
    }

    int h  = blockIdx.x >> 3;
    int w0 = (blockIdx.x & 7) << 4;

    int og = tid & 15;
    int pg = (tid >> 4) & 3;
    int ks = tid >> 6;
    const float4* wp = (const float4*)(sw + wrow_off(og*4)) + ks*18;      // +152 per o row
    const float4* pp = (const float4*)(ss + (pg*4)*SS_STRIDE) + ks*18;    // +145 per px row

    float bn_s = 0.f, bn_q = 0.f;

    #define COMPUTE_A(bb) { \
        int p = tid / 9, k = tid - p*9; \
        int w = w0 + p; \
        int ky = k / 3, kx = k - ky*3; \
        float dy = g_offset[(((bb)*18 + 2*k    )*Hv + h)*Wv + w]; \
        float dx = g_offset[(((bb)*18 + 2*k + 1)*Hv + h)*Wv + w]; \
        float m  = g_mask  [(((bb)*9  + k      )*Hv + h)*Wv + w]; \
        float py = (float)(h + ky - 1) + dy; \
        float px = (float)(w + kx - 1) + dx; \
        float y0f = floorf(py), x0f = floorf(px); \
        float wy1 = py - y0f, wx1 = px - x0f; \
        float wy0 = 1.f - wy1, wx0 = 1.f - wx1; \
        int iy0 = (int)y0f, ix0 = (int)x0f; \
        bool vy0 = (iy0 >= 0)  && (iy0 < Hv); \
        bool vy1 = (iy0 >= -1) && (iy0 < Hv-1); \
        bool vx0 = (ix0 >= 0)  && (ix0 < Wv); \
        bool vx1 = (ix0 >= -1) && (ix0 < Wv-1); \
        int y0c = min(Hv-1, max(0, iy0)); \
        int y1c = min(Hv-1, max(0, iy0 + 1)); \
        int x0c = min(Wv-1, max(0, ix0)); \
        int x1c = min(Wv-1, max(0, ix0 + 1)); \
        sAc[tid] = make_int4(y0c*Wv + x0c, y0c*Wv + x1c, y1c*Wv + x0c, y1c*Wv + x1c); \
        sAwf[tid] = make_float4((vy0 && vx0) ? m*wy0*wx0 : 0.f, \
                                (vy0 && vx1) ? m*wy0*wx1 : 0.f, \
                                (vy1 && vx0) ? m*wy1*wx0 : 0.f, \
                                (vy1 && vx1) ? m*wy1*wx1 : 0.f); \
    }

    #define GATH(dst, IT, xb4p) { \
        int pk_ = (IT) >> 4, cq_ = (IT) & 15; \
        int4 cc = sAc[pk_]; \
        float4 wg = sAwf[pk_]; \
        float4 v00 = (xb4p)[cc.x*16 + cq_]; \
        float4 v01 = (xb4p)[cc.y*16 + cq_]; \
        float4 v10 = (xb4p)[cc.z*16 + cq_]; \
        float4 v11 = (xb4p)[cc.w*16 + cq_]; \
        dst.x = fmaf(wg.w, v11.x, fmaf(wg.z, v10.x, fmaf(wg.y, v01.x, wg.x*v00.x))); \
        dst.y = fmaf(wg.w, v11.y, fmaf(wg.z, v10.y, fmaf(wg.y, v01.y, wg.x*v00.y))); \
        dst.z = fmaf(wg.w, v11.z, fmaf(wg.z, v10.z, fmaf(wg.y, v01.z, wg.x*v00.z))); \
        dst.w = fmaf(wg.w, v11.w, fmaf(wg.z, v10.w, fmaf(wg.y, v01.w, wg.x*v00.w))); \
    }

    #define STSG(src, IT) { \
        int pk_ = (IT) >> 4, cq_ = (IT) & 15; \
        int p_ = pk_ / 9, k_ = pk_ - p_*9; \
        ((float4*)(ss + p_*SS_STRIDE))[k_*16 + cq_] = src; \
    }

    if (tid < 144) COMPUTE_A(0);
    __syncthreads();   // weights + A(0) visible

    float4 g0, g1, g2, g3, g4;
    {
        const float4* xb4 = (const float4*)g_xt;
        GATH(g0, tid,        xb4);
        GATH(g1, 512 + tid,  xb4);
        GATH(g2, 1024 + tid, xb4);
        GATH(g3, 1536 + tid, xb4);
        if (tid < 256) GATH(g4, 2048 + tid, xb4);
    }
    __syncthreads();   // RACE FIX: prologue GATH(0) reads of sAc/sAw complete
                       // before iter 0's COMPUTE_A(1) overwrites them

    for (int b = 0; b < Bv; b++) {
        // write staged gather(b) to ss
        STSG(g0, tid);
        STSG(g1, 512 + tid);
        STSG(g2, 1024 + tid);
        STSG(g3, 1536 + tid);
        if (tid < 256) STSG(g4, 2048 + tid);
        if (b + 1 < Bv && tid < 144) COMPUTE_A(b+1);
        __syncthreads();   // X: ss(b) + A(b+1) ready

        // issue gather(b+1) into registers (latency hidden under GEMM)
        if (b + 1 < Bv) {
            const float4* xb4 = (const float4*)g_xt + (size_t)(b+1)*HWv*16;
            GATH(g0, tid,        xb4);
            GATH(g1, 512 + tid,  xb4);
            GATH(g2, 1024 + tid, xb4);
            GATH(g3, 1536 + tid, xb4);
            if (tid < 256) GATH(g4, 2048 + tid, xb4);
        }

        // GEMM: 16 accumulators (4 o x 4 p), 18 f4-chunks in this K-slice
        float a00=0,a01=0,a02=0,a03=0, a10=0,a11=0,a12=0,a13=0;
        float a20=0,a21=0,a22=0,a23=0, a30=0,a31=0,a32=0,a33=0;
        #pragma unroll
        for (int q = 0; q < 18; q++) {
            float4 qa = wp[q], qb = wp[q+152], qc = wp[q+304], qd = wp[q+456];
            float4 s0 = pp[q], s1 = pp[q+145], s2 = pp[q+290], s3 = pp[q+435];
            a00=fmaf(qa.x,s0.x,a00); a00=fmaf(qa.y,s0.y,a00); a00=fmaf(qa.z,s0.z,a00); a00=fmaf(qa.w,s0.w,a00);
            a01=fmaf(qa.x,s1.x,a01); a01=fmaf(qa.y,s1.y,a01); a01=fmaf(qa.z,s1.z,a01); a01=fmaf(qa.w,s1.w,a01);
            a02=fmaf(qa.x,s2.x,a02); a02=fmaf(qa.y,s2.y,a02); a02=fmaf(qa.z,s2.z,a02); a02=fmaf(qa.w,s2.w,a02);
            a03=fmaf(qa.x,s3.x,a03); a03=fmaf(qa.y,s3.y,a03); a03=fmaf(qa.z,s3.z,a03); a03=fmaf(qa.w,s3.w,a03);
            a10=fmaf(qb.x,s0.x,a10); a10=fmaf(qb.y,s0.y,a10); a10=fmaf(qb.z,s0.z,a10); a10=fmaf(qb.w,s0.w,a10);
            a11=fmaf(qb.x,s1.x,a11); a11=fmaf(qb.y,s1.y,a11); a11=fmaf(qb.z,s1.z,a11); a11=fmaf(qb.w,s1.w,a11);
            a12=fmaf(qb.x,s2.x,a12); a12=fmaf(qb.y,s2.y,a12); a12=fmaf(qb.z,s2.z,a12); a12=fmaf(qb.w,s2.w,a12);
            a13=fmaf(qb.x,s3.x,a13); a13=fmaf(qb.y,s3.y,a13); a13=fmaf(qb.z,s3.z,a13); a13=fmaf(qb.w,s3.w,a13);
            a20=fmaf(qc.x,s0.x,a20); a20=fmaf(qc.y,s0.y,a20); a20=fmaf(qc.z,s0.z,a20); a20=fmaf(qc.w,s0.w,a20);
            a21=fmaf(qc.x,s1.x,a21); a21=fmaf(qc.y,s1.y,a21); a21=fmaf(qc.z,s1.z,a21); a21=fmaf(qc.w,s1.w,a21);
            a22=fmaf(qc.x,s2.x,a22); a22=fmaf(qc.y,s2.y,a22); a22=fmaf(qc.z,s2.z,a22); a22=fmaf(qc.w,s2.w,a22);
            a23=fmaf(qc.x,s3.x,a23); a23=fmaf(qc.y,s3.y,a23); a23=fmaf(qc.z,s3.z,a23); a23=fmaf(qc.w,s3.w,a23);
            a30=fmaf(qd.x,s0.x,a30); a30=fmaf(qd.y,s0.y,a30); a30=fmaf(qd.z,s0.z,a30); a30=fmaf(qd.w,s0.w,a30);
            a31=fmaf(qd.x,s1.x,a31); a31=fmaf(qd.y,s1.y,a31); a31=fmaf(qd.z,s1.z,a31); a31=fmaf(qd.w,s1.w,a31);
            a32=fmaf(qd.x,s2.x,a32); a32=fmaf(qd.y,s2.y,a32); a32=fmaf(qd.z,s2.z,a32); a32=fmaf(qd.w,s2.w,a32);
            a33=fmaf(qd.x,s3.x,a33); a33=fmaf(qd.y,s3.y,a33); a33=fmaf(qd.z,s3.z,a33); a33=fmaf(qd.w,s3.w,a33);
        }
        {
            float4* rp = (float4*)red + ks*272 + og*17 + pg;
            rp[0]  = make_float4(a00,a01,a02,a03);
            rp[4]  = make_float4(a10,a11,a12,a13);
            rp[8]  = make_float4(a20,a21,a22,a23);
            rp[12] = make_float4(a30,a31,a32,a33);
        }
        __syncthreads();   // Y: red ready; all ss + sAc/sAw reads done

        if (tid < 256) {
            int o = tid >> 2, rpg = tid & 3;
            int base = (o >> 2)*17 + (o & 3)*4 + rpg;
            const float4* r4 = (const float4*)red;
            float4 v0 = r4[base];
            float4 v1 = r4[272  + base];
            float4 v2 = r4[544  + base];
            float4 v3 = r4[816  + base];
            float4 v4 = r4[1088 + base];
            float4 v5 = r4[1360 + base];
            float4 v6 = r4[1632 + base];
            float4 v7 = r4[1904 + base];
            float4 res;
            res.x = ((v0.x+v1.x)+(v2.x+v3.x)) + ((v4.x+v5.x)+(v6.x+v7.x));
            res.y = ((v0.y+v1.y)+(v2.y+v3.y)) + ((v4.y+v5.y)+(v6.y+v7.y));
            res.z = ((v0.z+v1.z)+(v2.z+v3.z)) + ((v4.z+v5.z)+(v6.z+v7.z));
            res.w = ((v0.w+v1.w)+(v2.w+v3.w)) + ((v4.w+v5.w)+(v6.w+v7.w));
            *(float4*)&out[((size_t)(b*Ov + o)*Hv + h)*Wv + w0 + rpg*4] = res;
            bn_s += (res.x + res.y) + (res.z + res.w);
            bn_q += fmaf(res.x,res.x, fmaf(res.y,res.y, fmaf(res.z,res.z, res.w*res.w)));
        }
    }

    if (tid < 256) {
        bn_s += __shfl_xor_sync(0xffffffff, bn_s, 1);
        bn_q += __shfl_xor_sync(0xffffffff, bn_q, 1);
        bn_s += __shfl_xor_sync(0xffffffff, bn_s, 2);
        bn_q += __shfl_xor_sync(0xffffffff, bn_q, 2);
        if ((tid & 3) == 0) {
            int o = tid >> 2;
            atomicAdd(&g_psum[o], bn_s);
            atomicAdd(&g_psq[o],  bn_q);
        }
    }
}

// ---------------------------------------------------------------------------
// BN stats (tiny) + normalize
// ---------------------------------------------------------------------------
__global__ void stats_kernel() {
    int c = threadIdx.x;
    const float inv = 1.f / (float)(Bv*HWv);
    float mean = g_psum[c] * inv;
    float var  = g_psq[c] * inv - mean*mean;
    g_mean[c] = mean;
    g_rstd[c] = rsqrtf(var + 1e-5f);
}

__global__ void bn_kernel(float* __restrict__ y,
                          const float* __restrict__ gamma,
                          const float* __restrict__ beta) {
    int idx = blockIdx.x*256 + threadIdx.x;
    if (idx >= Bv*Ov*HWv/4) return;
    int c = (idx >> 12) & 63;
    float a  = g_rstd[c] * gamma[c];
    float bb = fmaf(-g_mean[c], a, beta[c]);
    float4* p = (float4*)y;
    float4 v = p[idx];
    v.x = fmaxf(fmaf(v.x, a, bb), 0.f);
    v.y = fmaxf(fmaf(v.y, a, bb), 0.f);
    v.z = fmaxf(fmaf(v.z, a, bb), 0.f);
    v.w = fmaxf(fmaf(v.w, a, bb), 0.f);
    p[idx] = v;
}

// ---------------------------------------------------------------------------
extern "C" void kernel_launch(void* const* d_in, const int* in_sizes, int n_in,
                              void* d_out, int out_size) {
    const float* x     = (const float*)d_in[0];
    const float* wh    = (const float*)d_in[1];
    const float* bh    = (const float*)d_in[2];
    const float* wv    = (const float*)d_in[3];
    const float* bv    = (const float*)d_in[4];
    const float* wm    = (const float*)d_in[5];
    const float* bm    = (const float*)d_in[6];
    const float* wd    = (const float*)d_in[7];
    const float* gamma = (const float*)d_in[8];
    const float* beta  = (const float*)d_in[9];
    float* out = (float*)d_out;

    const int deform_smem = SMEM_FLOATS * 4;   // 232192 B
    cudaFuncSetAttribute(deform_kernel, cudaFuncAttributeMaxDynamicSharedMemorySize, deform_smem);

    pack_kernel<<<(18432 + 6912 + 36864 + 255)/256, 256>>>(wh, wv, wm, wd);
    transpose_kernel<<<dim3(HWv/32, Cv/32, Bv), dim3(32, 8)>>>(x);
    offmask_kernel<<<dim3(Wv/32, Hv/8, Bv), 128>>>(x, bh, bv, bm);
    deform_kernel<<<1024, 512, deform_smem>>>(out);
    stats_kernel<<<1, Ov>>>();
    bn_kernel<<<(Bv*Ov*HWv/4 + 255)/256, 256>>>(out, gamma, beta);
}

// round 12
// speedup vs baseline: 1.5608x; 1.0047x over previous
#include <cuda_runtime.h>
#include <math.h>

#define Bv 8
#define Cv 64
#define Hv 128
#define Wv 128
#define Ov 64
#define HWv (Hv*Wv)

typedef unsigned long long u64;

__device__ __forceinline__ u64 ffma2(u64 a, u64 b, u64 c) {
    u64 d;
    asm("fma.rn.f32x2 %0, %1, %2, %3;" : "=l"(d) : "l"(a), "l"(b), "l"(c));
    return d;
}
__device__ __forceinline__ float unpk_sum(u64 v) {
    unsigned lo, hi;
    asm("mov.b64 {%0, %1}, %2;" : "=r"(lo), "=r"(hi) : "l"(v));
    return __uint_as_float(lo) + __uint_as_float(hi);
}

// scratch (__device__ globals; no allocation allowed)
__device__ float g_offset[Bv*18*HWv];   // (B,18,H,W)
__device__ float g_mask[Bv*9*HWv];      // (B,9,H,W)
__device__ float g_xt[(size_t)Bv*HWv*Cv]; // (B,H,W,C)
__device__ float g_whP[Cv*18*16];
__device__ float g_wvP[Cv*18*16];
__device__ float g_wmP[Cv*9*12];
__device__ float g_wdT[Ov*576];         // [o][j], j = k*16 + c/4 (float4 granules)
__device__ float g_psum[Ov];
__device__ float g_psq[Ov];
__device__ float g_mean[Ov];
__device__ float g_rstd[Ov];

// ---------------------------------------------------------------------------
// weight packer (+ zero the fused BN accumulators each launch)
// ---------------------------------------------------------------------------
__global__ void pack_kernel(const float* __restrict__ wh, const float* __restrict__ wv,
                            const float* __restrict__ wm, const float* __restrict__ wd) {
    int idx = blockIdx.x*256 + threadIdx.x;
    if (blockIdx.x == 0 && threadIdx.x < Ov) {
        g_psum[threadIdx.x] = 0.f;
        g_psq[threadIdx.x]  = 0.f;
    }
    if (idx < 18432) {
        int c = idx/288, r = idx - c*288, o = r >> 4, k = r & 15;
        g_whP[idx] = (k < 15) ? wh[(o*Cv + c)*15 + k] : 0.f;
        g_wvP[idx] = (k < 15) ? wv[(o*Cv + c)*15 + k] : 0.f;
    } else if (idx < 18432 + 6912) {
        int j = idx - 18432;
        int c = j/108, r = j - c*108, o = r/12, k = r - o*12;
        g_wmP[j] = (k < 9) ? wm[(o*Cv + c)*9 + k] : 0.f;
    } else if (idx < 18432 + 6912 + 36864) {
        int j = idx - 18432 - 6912;
        int o = j/576, r = j - o*576, k = r >> 6, c = r & 63;
        g_wdT[j] = wd[(o*Cv + c)*9 + k];
    }
}

// ---------------------------------------------------------------------------
// x (B,C,HW) -> xt (B,HW,C)
// ---------------------------------------------------------------------------
__global__ void transpose_kernel(const float* __restrict__ x) {
    __shared__ float t[32][33];
    int b = blockIdx.z;
    int hw0 = blockIdx.x * 32;
    int c0  = blockIdx.y * 32;
    int tx = threadIdx.x, ty = threadIdx.y;
    #pragma unroll
    for (int j = 0; j < 4; j++) {
        int c = c0 + ty + j*8;
        t[ty + j*8][tx] = x[((size_t)b*Cv + c)*HWv + hw0 + tx];
    }
    __syncthreads();
    #pragma unroll
    for (int j = 0; j < 4; j++) {
        int hw = hw0 + ty + j*8;
        g_xt[((size_t)b*HWv + hw)*Cv + c0 + tx] = t[tx][ty + j*8];
    }
}

// ---------------------------------------------------------------------------
// fused offset(18ch) + mask(9ch), 32x8 tile, 128 threads, 2 px/thread
// ---------------------------------------------------------------------------
__global__ void __launch_bounds__(128, 4) offmask_kernel(
    const float* __restrict__ x,
    const float* __restrict__ bh, const float* __restrict__ bv,
    const float* __restrict__ bm)
{
    __shared__ float tiles[2][22*47];
    int b  = blockIdx.z;
    int h0 = blockIdx.y * 8;
    int wb = blockIdx.x * 32;
    int tid = threadIdx.x;
    int tx = tid & 15, ty = tid >> 4;
    int h = h0 + ty;
    int w = wb + 2*tx;

    int  soff[8], sidx[8];
    #pragma unroll
    for (int s = 0; s < 8; s++) {
        int i = tid + s*128;
        if (i < 22*46) {
            int r = i / 46, cc = i - r*46;
            int gh = h0 + r - 7, gw = wb + cc - 7;
            sidx[s] = r*47 + cc;
            soff[s] = (gh >= 0 && gh < Hv && gw >= 0 && gw < Wv) ? gh*Wv + gw : -1;
        } else { sidx[s] = -1; soff[s] = -1; }
    }

    float acc0[18], acc1[18], am0[9], am1[9];
    #pragma unroll
    for (int o = 0; o < 18; o++) { float bo = bh[o] + bv[o]; acc0[o] = bo; acc1[o] = bo; }
    #pragma unroll
    for (int o = 0; o < 9; o++)  { float bo = bm[o]; am0[o] = bo; am1[o] = bo; }

    const float* xb = x + (size_t)b*Cv*HWv;

    {
        const float* xc = xb;
        #pragma unroll
        for (int s = 0; s < 8; s++)
            if (sidx[s] >= 0) tiles[0][sidx[s]] = (soff[s] >= 0) ? __ldg(xc + soff[s]) : 0.f;
    }

    for (int c = 0; c < Cv; c++) {
        __syncthreads();
        if (c + 1 < Cv) {
            const float* xc = xb + (c+1)*HWv;
            float* dst = tiles[(c+1) & 1];
            #pragma unroll
            for (int s = 0; s < 8; s++)
                if (sidx[s] >= 0) dst[sidx[s]] = (soff[s] >= 0) ? __ldg(xc + soff[s]) : 0.f;
        }
        const float* tile = tiles[c & 1];

        float xr[16];
        #pragma unroll
        for (int i = 0; i < 16; i++) xr[i] = tile[(ty+7)*47 + 2*tx + i];
        float xcA[15], xcB[15];
        #pragma unroll
        for (int i = 0; i < 15; i++) {
            xcA[i] = tile[(ty+i)*47 + 2*tx + 7];
            xcB[i] = tile[(ty+i)*47 + 2*tx + 8];
        }
        float t00 = tile[(ty+6)*47 + 2*tx + 6];
        float t01 = tile[(ty+6)*47 + 2*tx + 9];
        float t10 = tile[(ty+8)*47 + 2*tx + 6];
        float t11 = tile[(ty+8)*47 + 2*tx + 9];

        const float4* whc = (const float4*)(g_whP + c*288);
        const float4* wvc = (const float4*)(g_wvP + c*288);
        const float4* wmc = (const float4*)(g_wmP + c*108);
        #pragma unroll
        for (int o = 0; o < 18; o++) {
            float4 q0 = whc[o*4+0], q1 = whc[o*4+1], q2 = whc[o*4+2], q3 = whc[o*4+3];
            float wkh[15] = {q0.x,q0.y,q0.z,q0.w, q1.x,q1.y,q1.z,q1.w,
                             q2.x,q2.y,q2.z,q2.w, q3.x,q3.y,q3.z};
            float a0 = acc0[o], a1 = acc1[o];
            #pragma unroll
            for (int k = 0; k < 15; k++) {
                a0 = fmaf(xr[k],   wkh[k], a0);
                a1 = fmaf(xr[k+1], wkh[k], a1);
            }
            float4 v0 = wvc[o*4+0], v1 = wvc[o*4+1], v2 = wvc[o*4+2], v3 = wvc[o*4+3];
            float wkv[15] = {v0.x,v0.y,v0.z,v0.w, v1.x,v1.y,v1.z,v1.w,
                             v2.x,v2.y,v2.z,v2.w, v3.x,v3.y,v3.z};
            #pragma unroll
            for (int k = 0; k < 15; k++) {
                a0 = fmaf(xcA[k], wkv[k], a0);
                a1 = fmaf(xcB[k], wkv[k], a1);
            }
            acc0[o] = a0; acc1[o] = a1;
        }
        #pragma unroll
        for (int o = 0; o < 9; o++) {
            float4 q0 = wmc[o*3], q1 = wmc[o*3+1], q2 = wmc[o*3+2];
            float m0 = am0[o], m1 = am1[o];
            m0 = fmaf(t00,    q0.x, m0);  m1 = fmaf(xcA[6], q0.x, m1);
            m0 = fmaf(xcA[6], q0.y, m0);  m1 = fmaf(xcB[6], q0.y, m1);
            m0 = fmaf(xcB[6], q0.z, m0);  m1 = fmaf(t01,    q0.z, m1);
            m0 = fmaf(xr[6],  q0.w, m0);  m1 = fmaf(xr[7],  q0.w, m1);
            m0 = fmaf(xr[7],  q1.x, m0);  m1 = fmaf(xr[8],  q1.x, m1);
            m0 = fmaf(xr[8],  q1.y, m0);  m1 = fmaf(xr[9],  q1.y, m1);
            m0 = fmaf(t10,    q1.z, m0);  m1 = fmaf(xcA[8], q1.z, m1);
            m0 = fmaf(xcA[8], q1.w, m0);  m1 = fmaf(xcB[8], q1.w, m1);
            m0 = fmaf(xcB[8], q2.x, m0);  m1 = fmaf(t11,    q2.x, m1);
            am0[o] = m0; am1[o] = m1;
        }
    }

    #pragma unroll
    for (int o = 0; o < 18; o++) {
        float2 v; v.x = acc0[o]; v.y = acc1[o];
        *(float2*)&g_offset[((b*18 + o)*Hv + h)*Wv + w] = v;
    }
    #pragma unroll
    for (int o = 0; o < 9; o++) {
        float2 v;
        v.x = 1.f/(1.f + __expf(-am0[o]));
        v.y = 1.f/(1.f + __expf(-am1[o]));
        *(float2*)&g_mask[((b*9 + o)*Hv + h)*Wv + w] = v;
    }
}

// ---------------------------------------------------------------------------
// deform, software-pipelined; stage C uses packed fma.rn.f32x2 over K-pairs
// (operands come pre-packed from 16B smem loads; accumulators are (even,odd)
// K-partials, unpacked once in the epilogue)
// ---------------------------------------------------------------------------
#define SW_STRIDE 608
#define SW_FLOATS 38912
#define SS_STRIDE 580
#define OFF_SS   SW_FLOATS                    // 9280 floats
#define OFF_RED  (OFF_SS + 16*SS_STRIDE)      // 8704 floats
#define OFF_SAC  (OFF_RED + 8*1088)           // int4[144] = 576 floats
#define OFF_SAW  (OFF_SAC + 576)              // float4[144] = 576 floats
#define SMEM_FLOATS (OFF_SAW + 576)           // 58048 floats = 232192 B

__device__ __forceinline__ int wrow_off(int o) {
    return o*SW_STRIDE + ((o >> 2) & 7)*4;
}

__global__ void __launch_bounds__(512, 1) deform_kernel(float* __restrict__ out) {
    extern __shared__ float smem[];
    float* sw   = smem;
    float* ss   = smem + OFF_SS;
    float* red  = smem + OFF_RED;
    int4*  sAc  = (int4*)(smem + OFF_SAC);
    float4* sAwf = (float4*)(smem + OFF_SAW);
    int tid = threadIdx.x;

    const float4* wt4 = (const float4*)g_wdT;
    for (int i = tid; i < 64*144; i += 512) {
        int o = i / 144, q = i - o*144;
        ((float4*)(sw + wrow_off(o)))[q] = wt4[i];
    }

    int h  = blockIdx.x >> 3;
    int w0 = (blockIdx.x & 7) << 4;

    int og = tid & 15;
    int pg = (tid >> 4) & 3;
    int ks = tid >> 6;
    const ulonglong2* wp = (const ulonglong2*)(sw + wrow_off(og*4)) + ks*18;   // +152/row
    const ulonglong2* pp = (const ulonglong2*)(ss + (pg*4)*SS_STRIDE) + ks*18; // +145/row

    float bn_s = 0.f, bn_q = 0.f;

    #define COMPUTE_A(bb) { \
        int p = tid / 9, k = tid - p*9; \
        int w = w0 + p; \
        int ky = k / 3, kx = k - ky*3; \
        float dy = g_offset[(((bb)*18 + 2*k    )*Hv + h)*Wv + w]; \
        float dx = g_offset[(((bb)*18 + 2*k + 1)*Hv + h)*Wv + w]; \
        float m  = g_mask  [(((bb)*9  + k      )*Hv + h)*Wv + w]; \
        float py = (float)(h + ky - 1) + dy; \
        float px = (float)(w + kx - 1) + dx; \
        float y0f = floorf(py), x0f = floorf(px); \
        float wy1 = py - y0f, wx1 = px - x0f; \
        float wy0 = 1.f - wy1, wx0 = 1.f - wx1; \
        int iy0 = (int)y0f, ix0 = (int)x0f; \
        bool vy0 = (iy0 >= 0)  && (iy0 < Hv); \
        bool vy1 = (iy0 >= -1) && (iy0 < Hv-1); \
        bool vx0 = (ix0 >= 0)  && (ix0 < Wv); \
        bool vx1 = (ix0 >= -1) && (ix0 < Wv-1); \
        int y0c = min(Hv-1, max(0, iy0)); \
        int y1c = min(Hv-1, max(0, iy0 + 1)); \
        int x0c = min(Wv-1, max(0, ix0)); \
        int x1c = min(Wv-1, max(0, ix0 + 1)); \
        sAc[tid] = make_int4(y0c*Wv + x0c, y0c*Wv + x1c, y1c*Wv + x0c, y1c*Wv + x1c); \
        sAwf[tid] = make_float4((vy0 && vx0) ? m*wy0*wx0 : 0.f, \
                                (vy0 && vx1) ? m*wy0*wx1 : 0.f, \
                                (vy1 && vx0) ? m*wy1*wx0 : 0.f, \
                                (vy1 && vx1) ? m*wy1*wx1 : 0.f); \
    }

    #define GATH(dst, IT, xb4p) { \
        int pk_ = (IT) >> 4, cq_ = (IT) & 15; \
        int4 cc = sAc[pk_]; \
        float4 wg = sAwf[pk_]; \
        float4 v00 = (xb4p)[cc.x*16 + cq_]; \
        float4 v01 = (xb4p)[cc.y*16 + cq_]; \
        float4 v10 = (xb4p)[cc.z*16 + cq_]; \
        float4 v11 = (xb4p)[cc.w*16 + cq_]; \
        dst.x = fmaf(wg.w, v11.x, fmaf(wg.z, v10.x, fmaf(wg.y, v01.x, wg.x*v00.x))); \
        dst.y = fmaf(wg.w, v11.y, fmaf(wg.z, v10.y, fmaf(wg.y, v01.y, wg.x*v00.y))); \
        dst.z = fmaf(wg.w, v11.z, fmaf(wg.z, v10.z, fmaf(wg.y, v01.z, wg.x*v00.z))); \
        dst.w = fmaf(wg.w, v11.w, fmaf(wg.z, v10.w, fmaf(wg.y, v01.w, wg.x*v00.w))); \
    }

    #define STSG(src, IT) { \
        int pk_ = (IT) >> 4, cq_ = (IT) & 15; \
        int p_ = pk_ / 9, k_ = pk_ - p_*9; \
        ((float4*)(ss + p_*SS_STRIDE))[k_*16 + cq_] = src; \
    }

    if (tid < 144) COMPUTE_A(0);
    __syncthreads();   // weights + A(0) visible

    float4 g0, g1, g2, g3, g4;
    {
        const float4* xb4 = (const float4*)g_xt;
        GATH(g0, tid,        xb4);
        GATH(g1, 512 + tid,  xb4);
        GATH(g2, 1024 + tid, xb4);
        GATH(g3, 1536 + tid, xb4);
        if (tid < 256) GATH(g4, 2048 + tid, xb4);
    }
    __syncthreads();   // prologue GATH(0) reads complete before COMPUTE_A(1)

    for (int b = 0; b < Bv; b++) {
        STSG(g0, tid);
        STSG(g1, 512 + tid);
        STSG(g2, 1024 + tid);
        STSG(g3, 1536 + tid);
        if (tid < 256) STSG(g4, 2048 + tid);
        if (b + 1 < Bv && tid < 144) COMPUTE_A(b+1);
        __syncthreads();   // X: ss(b) + A(b+1) ready

        if (b + 1 < Bv) {
            const float4* xb4 = (const float4*)g_xt + (size_t)(b+1)*HWv*16;
            GATH(g0, tid,        xb4);
            GATH(g1, 512 + tid,  xb4);
            GATH(g2, 1024 + tid, xb4);
            GATH(g3, 1536 + tid, xb4);
            if (tid < 256) GATH(g4, 2048 + tid, xb4);
        }

        // GEMM with packed f32x2: 16 packed acc (4 o x 4 p), 18 16B-chunks
        u64 A00=0,A01=0,A02=0,A03=0, A10=0,A11=0,A12=0,A13=0;
        u64 A20=0,A21=0,A22=0,A23=0, A30=0,A31=0,A32=0,A33=0;
        #pragma unroll
        for (int q = 0; q < 18; q++) {
            ulonglong2 qa = wp[q], qb = wp[q+152], qc = wp[q+304], qd = wp[q+456];
            ulonglong2 s0 = pp[q], s1 = pp[q+145], s2 = pp[q+290], s3 = pp[q+435];
            A00 = ffma2(qa.x, s0.x, A00); A00 = ffma2(qa.y, s0.y, A00);
            A01 = ffma2(qa.x, s1.x, A01); A01 = ffma2(qa.y, s1.y, A01);
            A02 = ffma2(qa.x, s2.x, A02); A02 = ffma2(qa.y, s2.y, A02);
            A03 = ffma2(qa.x, s3.x, A03); A03 = ffma2(qa.y, s3.y, A03);
            A10 = ffma2(qb.x, s0.x, A10); A10 = ffma2(qb.y, s0.y, A10);
            A11 = ffma2(qb.x, s1.x, A11); A11 = ffma2(qb.y, s1.y, A11);
            A12 = ffma2(qb.x, s2.x, A12); A12 = ffma2(qb.y, s2.y, A12);
            A13 = ffma2(qb.x, s3.x, A13); A13 = ffma2(qb.y, s3.y, A13);
            A20 = ffma2(qc.x, s0.x, A20); A20 = ffma2(qc.y, s0.y, A20);
            A21 = ffma2(qc.x, s1.x, A21); A21 = ffma2(qc.y, s1.y, A21);
            A22 = ffma2(qc.x, s2.x, A22); A22 = ffma2(qc.y, s2.y, A22);
            A23 = ffma2(qc.x, s3.x, A23); A23 = ffma2(qc.y, s3.y, A23);
            A30 = ffma2(qd.x, s0.x, A30); A30 = ffma2(qd.y, s0.y, A30);
            A31 = ffma2(qd.x, s1.x, A31); A31 = ffma2(qd.y, s1.y, A31);
            A32 = ffma2(qd.x, s2.x, A32); A32 = ffma2(qd.y, s2.y, A32);
            A33 = ffma2(qd.x, s3.x, A33); A33 = ffma2(qd.y, s3.y, A33);
        }
        {
            float4* rp = (float4*)red + ks*272 + og*17 + pg;
            rp[0]  = make_float4(unpk_sum(A00), unpk_sum(A01), unpk_sum(A02), unpk_sum(A03));
            rp[4]  = make_float4(unpk_sum(A10), unpk_sum(A11), unpk_sum(A12), unpk_sum(A13));
            rp[8]  = make_float4(unpk_sum(A20), unpk_sum(A21), unpk_sum(A22), unpk_sum(A23));
            rp[12] = make_float4(unpk_sum(A30), unpk_sum(A31), unpk_sum(A32), unpk_sum(A33));
        }
        __syncthreads();   // Y: red ready; all ss + sAc/sAw reads done

        if (tid < 256) {
            int o = tid >> 2, rpg = tid & 3;
            int base = (o >> 2)*17 + (o & 3)*4 + rpg;
            const float4* r4 = (const float4*)red;
            float4 v0 = r4[base];
            float4 v1 = r4[272  + base];
            float4 v2 = r4[544  + base];
            float4 v3 = r4[816  + base];
            float4 v4 = r4[1088 + base];
            float4 v5 = r4[1360 + base];
            float4 v6 = r4[1632 + base];
            float4 v7 = r4[1904 + base];
            float4 res;
            res.x = ((v0.x+v1.x)+(v2.x+v3.x)) + ((v4.x+v5.x)+(v6.x+v7.x));
            res.y = ((v0.y+v1.y)+(v2.y+v3.y)) + ((v4.y+v5.y)+(v6.y+v7.y));
            res.z = ((v0.z+v1.z)+(v2.z+v3.z)) + ((v4.z+v5.z)+(v6.z+v7.z));
            res.w = ((v0.w+v1.w)+(v2.w+v3.w)) + ((v4.w+v5.w)+(v6.w+v7.w));
            *(float4*)&out[((size_t)(b*Ov + o)*Hv + h)*Wv + w0 + rpg*4] = res;
            bn_s += (res.x + res.y) + (res.z + res.w);
            bn_q += fmaf(res.x,res.x, fmaf(res.y,res.y, fmaf(res.z,res.z, res.w*res.w)));
        }
    }

    if (tid < 256) {
        bn_s += __shfl_xor_sync(0xffffffff, bn_s, 1);
        bn_q += __shfl_xor_sync(0xffffffff, bn_q, 1);
        bn_s += __shfl_xor_sync(0xffffffff, bn_s, 2);
        bn_q += __shfl_xor_sync(0xffffffff, bn_q, 2);
        if ((tid & 3) == 0) {
            int o = tid >> 2;
            atomicAdd(&g_psum[o], bn_s);
            atomicAdd(&g_psq[o],  bn_q);
        }
    }
}

// ---------------------------------------------------------------------------
// BN stats (tiny) + normalize
// ---------------------------------------------------------------------------
__global__ void stats_kernel() {
    int c = threadIdx.x;
    const float inv = 1.f / (float)(Bv*HWv);
    float mean = g_psum[c] * inv;
    float var  = g_psq[c] * inv - mean*mean;
    g_mean[c] = mean;
    g_rstd[c] = rsqrtf(var + 1e-5f);
}

__global__ void bn_kernel(float* __restrict__ y,
                          const float* __restrict__ gamma,
                          const float* __restrict__ beta) {
    int idx = blockIdx.x*256 + threadIdx.x;
    if (idx >= Bv*Ov*HWv/4) return;
    int c = (idx >> 12) & 63;
    float a  = g_rstd[c] * gamma[c];
    float bb = fmaf(-g_mean[c], a, beta[c]);
    float4* p = (float4*)y;
    float4 v = p[idx];
    v.x = fmaxf(fmaf(v.x, a, bb), 0.f);
    v.y = fmaxf(fmaf(v.y, a, bb), 0.f);
    v.z = fmaxf(fmaf(v.z, a, bb), 0.f);
    v.w = fmaxf(fmaf(v.w, a, bb), 0.f);
    p[idx] = v;
}

// ---------------------------------------------------------------------------
extern "C" void kernel_launch(void* const* d_in, const int* in_sizes, int n_in,
                              void* d_out, int out_size) {
    const float* x     = (const float*)d_in[0];
    const float* wh    = (const float*)d_in[1];
    const float* bh    = (const float*)d_in[2];
    const float* wv    = (const float*)d_in[3];
    const float* bv    = (const float*)d_in[4];
    const float* wm    = (const float*)d_in[5];
    const float* bm    = (const float*)d_in[6];
    const float* wd    = (const float*)d_in[7];
    const float* gamma = (const float*)d_in[8];
    const float* beta  = (const float*)d_in[9];
    float* out = (float*)d_out;

    const int deform_smem = SMEM_FLOATS * 4;   // 232192 B
    cudaFuncSetAttribute(deform_kernel, cudaFuncAttributeMaxDynamicSharedMemorySize, deform_smem);

    pack_kernel<<<(18432 + 6912 + 36864 + 255)/256, 256>>>(wh, wv, wm, wd);
    transpose_kernel<<<dim3(HWv/32, Cv/32, Bv), dim3(32, 8)>>>(x);
    offmask_kernel<<<dim3(Wv/32, Hv/8, Bv), 128>>>(x, bh, bv, bm);
    deform_kernel<<<1024, 512, deform_smem>>>(out);
    stats_kernel<<<1, Ov>>>();
    bn_kernel<<<(Bv*Ov*HWv/4 + 255)/256, 256>>>(out, gamma, beta);
}